// round 2
// baseline (speedup 1.0000x reference)
#include <cuda_runtime.h>
#include <cuda_bf16.h>
#include <math.h>

// Problem constants
#define BB 2
#define SS 2048
#define DD 1024
#define HH 16
#define DK 64
#define NROWS (BB * SS)   // 4096

// ---------------------------------------------------------------------------
// Scratch (device globals -- no allocation allowed)
// ---------------------------------------------------------------------------
__device__ float g_q[NROWS * DD];
__device__ float g_k[NROWS * DD];
__device__ float g_v[NROWS * DD];
__device__ float g_x[NROWS * DD];

// ---------------------------------------------------------------------------
// SGEMM: Y[n,o] = sum_d X[n,d] * W[o,d]
// M = 4096, N = 1024, K = 1024 (fixed). 128x128 tile, 16-K step,
// 256 threads, 8x8 per thread, double-buffered smem, float4 everywhere.
// grid = (N/128, M/128) = (8, 32)
// ---------------------------------------------------------------------------
__global__ __launch_bounds__(256, 2) void sgemm4096(
    const float* __restrict__ X, const float* __restrict__ W,
    float* __restrict__ Y) {
  __shared__ float As[2][16][132];
  __shared__ float Bs[2][16][132];
  const int t = threadIdx.x;
  const int m0 = blockIdx.y * 128;
  const int n0 = blockIdx.x * 128;

  const int lrow = t >> 2;          // 0..63 (rows lrow and lrow+64)
  const int lk = (t & 3) << 2;      // k offset 0,4,8,12
  const float* xp = X + (size_t)(m0 + lrow) * 1024 + lk;
  const float* wp = W + (size_t)(n0 + lrow) * 1024 + lk;

  float4 a0 = *(const float4*)(xp);
  float4 a1 = *(const float4*)(xp + (size_t)64 * 1024);
  float4 b0 = *(const float4*)(wp);
  float4 b1 = *(const float4*)(wp + (size_t)64 * 1024);

  int buf = 0;
#define SSTORE()                                                        \
  do {                                                                  \
    As[buf][lk + 0][lrow] = a0.x; As[buf][lk + 1][lrow] = a0.y;         \
    As[buf][lk + 2][lrow] = a0.z; As[buf][lk + 3][lrow] = a0.w;         \
    As[buf][lk + 0][lrow + 64] = a1.x; As[buf][lk + 1][lrow + 64] = a1.y; \
    As[buf][lk + 2][lrow + 64] = a1.z; As[buf][lk + 3][lrow + 64] = a1.w; \
    Bs[buf][lk + 0][lrow] = b0.x; Bs[buf][lk + 1][lrow] = b0.y;         \
    Bs[buf][lk + 2][lrow] = b0.z; Bs[buf][lk + 3][lrow] = b0.w;         \
    Bs[buf][lk + 0][lrow + 64] = b1.x; Bs[buf][lk + 1][lrow + 64] = b1.y; \
    Bs[buf][lk + 2][lrow + 64] = b1.z; Bs[buf][lk + 3][lrow + 64] = b1.w; \
  } while (0)

  SSTORE();
  __syncthreads();

  const int tm = (t >> 4) << 3;     // 0..120
  const int tn = (t & 15) << 3;     // 0..120
  float acc[8][8] = {};

  for (int kt = 0; kt < 64; kt++) {
    if (kt < 63) {
      const float* xn = xp + (kt + 1) * 16;
      const float* wn = wp + (kt + 1) * 16;
      a0 = *(const float4*)(xn);
      a1 = *(const float4*)(xn + (size_t)64 * 1024);
      b0 = *(const float4*)(wn);
      b1 = *(const float4*)(wn + (size_t)64 * 1024);
    }
#pragma unroll
    for (int kk = 0; kk < 16; kk++) {
      float4 xa0 = *(const float4*)&As[buf][kk][tm];
      float4 xa1 = *(const float4*)&As[buf][kk][tm + 4];
      float4 xb0 = *(const float4*)&Bs[buf][kk][tn];
      float4 xb1 = *(const float4*)&Bs[buf][kk][tn + 4];
      float av[8] = {xa0.x, xa0.y, xa0.z, xa0.w, xa1.x, xa1.y, xa1.z, xa1.w};
      float bv[8] = {xb0.x, xb0.y, xb0.z, xb0.w, xb1.x, xb1.y, xb1.z, xb1.w};
#pragma unroll
      for (int i = 0; i < 8; i++)
#pragma unroll
        for (int j = 0; j < 8; j++) acc[i][j] += av[i] * bv[j];
    }
    if (kt < 63) {
      buf ^= 1;
      SSTORE();
      __syncthreads();
    }
  }
#undef SSTORE

#pragma unroll
  for (int i = 0; i < 8; i++) {
    float4 o0 = {acc[i][0], acc[i][1], acc[i][2], acc[i][3]};
    float4 o1 = {acc[i][4], acc[i][5], acc[i][6], acc[i][7]};
    float* yp = Y + (size_t)(m0 + tm + i) * 1024 + n0 + tn;
    *(float4*)(yp) = o0;
    *(float4*)(yp + 4) = o1;
  }
}

// ---------------------------------------------------------------------------
// RoPE (pairwise-interleaved variant, matching the reference exactly):
//   out0 = x0*cos(a(2i)) - x1*sin(a(2i))
//   out1 = x0*sin(a(2i+1)) + x1*cos(a(2i+1))
// a(j) = s * 10000^{-(j mod 32)/32}.  Angle formed in fp32 (like reference),
// range-reduced in double for accurate cos/sin at large angles.
// ---------------------------------------------------------------------------
__global__ void rope_kernel(float* __restrict__ Q, float* __restrict__ K) {
  const int total = BB * SS * HH * (DK / 2);  // 2,097,152
  int p = blockIdx.x * blockDim.x + threadIdx.x;
  if (p >= total) return;
  const int i = p & 31;                 // pair index within head
  const int s = (p >> 9) & (SS - 1);    // sequence position
  const int m0 = (2 * i) & 31;
  const int m1 = (2 * i + 1) & 31;
  const float L = 0.41524101186091903f;  // log2(10000)/32
  float a0 = (float)s * exp2f(-(float)m0 * L);
  float a1 = (float)s * exp2f(-(float)m1 * L);
  const double INV2PI = 0.15915494309189535;
  const double TWOPI = 6.283185307179586;
  double r0 = (double)a0 - floor((double)a0 * INV2PI) * TWOPI;
  double r1 = (double)a1 - floor((double)a1 * INV2PI) * TWOPI;
  float c0 = cosf((float)r0), s0 = sinf((float)r0);
  float c1 = cosf((float)r1), s1 = sinf((float)r1);

  float2* q2 = (float2*)Q;
  float2* k2 = (float2*)K;
  float2 xq = q2[p];
  float2 xk = k2[p];
  float2 oq, ok;
  oq.x = xq.x * c0 - xq.y * s0;
  oq.y = xq.x * s1 + xq.y * c1;
  ok.x = xk.x * c0 - xk.y * s0;
  ok.y = xk.x * s1 + xk.y * c1;
  q2[p] = oq;
  k2[p] = ok;
}

// ---------------------------------------------------------------------------
// Flash attention, causal, fp32. One CTA = 64 query rows of one (b,h).
// 256 threads, 4x4 register tile per thread over the 64x64 score tile.
// Q, K, P tiles stored TRANSPOSED in smem ([dim][row], stride 68) so the
// inner loops use float4 LDS: 2x LDS.128 + 16 FMA per k-step (FMA-bound).
// dyn smem: Qt,Kt,Vs,Pt each 64x68 floats = 69632 B total.
// grid = (B*H=32, S/64=32); qt reversed so long-loop blocks start first.
// ---------------------------------------------------------------------------
#define TST 68
#define ATTN_SMEM (4 * 64 * TST * 4)

__global__ __launch_bounds__(256) void flash_attn(
    const float* __restrict__ Q, const float* __restrict__ K,
    const float* __restrict__ V, float* __restrict__ Xo) {
  extern __shared__ float sm[];
  float* Qt = sm;                  // [dim][qrow]
  float* Kt = sm + 64 * TST;       // [dim][krow]
  float* Vs = sm + 2 * 64 * TST;   // [krow][dim]
  float* Pt = sm + 3 * 64 * TST;   // [kcol][qrow]

  const int t = threadIdx.x;
  const int bh = blockIdx.x;
  const int b = bh >> 4;
  const int h = bh & 15;
  const int qt = (int)gridDim.y - 1 - (int)blockIdx.y;  // heavy blocks first
  const size_t base = (size_t)b * SS * DD + h * DK;

  // Load Q tile [64 rows x 64 dims], store transposed Qt[dim][row]
  for (int idx = t; idx < 1024; idx += 256) {
    int rr = idx >> 4;
    int c4 = (idx & 15) << 2;
    float4 v = *(const float4*)(Q + base + (size_t)(qt * 64 + rr) * DD + c4);
    Qt[(c4 + 0) * TST + rr] = v.x;
    Qt[(c4 + 1) * TST + rr] = v.y;
    Qt[(c4 + 2) * TST + rr] = v.z;
    Qt[(c4 + 3) * TST + rr] = v.w;
  }

  const int rg = (t >> 4) << 2;  // this thread's 4 q-rows
  const int cg = (t & 15) << 2;  // this thread's 4 k-cols / v-dims
  float mrow[4] = {-INFINITY, -INFINITY, -INFINITY, -INFINITY};
  float lrow[4] = {0.f, 0.f, 0.f, 0.f};
  float o[4][4] = {};
  __syncthreads();

  for (int kt = 0; kt <= qt; kt++) {
    // Load K (transposed) and V tiles
    for (int idx = t; idx < 1024; idx += 256) {
      int rr = idx >> 4;
      int c4 = (idx & 15) << 2;
      size_t g = base + (size_t)(kt * 64 + rr) * DD + c4;
      float4 kv = *(const float4*)(K + g);
      float4 vv = *(const float4*)(V + g);
      Kt[(c4 + 0) * TST + rr] = kv.x;
      Kt[(c4 + 1) * TST + rr] = kv.y;
      Kt[(c4 + 2) * TST + rr] = kv.z;
      Kt[(c4 + 3) * TST + rr] = kv.w;
      float* dv = &Vs[rr * TST + c4];
      dv[0] = vv.x; dv[1] = vv.y; dv[2] = vv.z; dv[3] = vv.w;
    }
    __syncthreads();

    // S = Q K^T (4x4 per thread), float4 LDS on both operands
    float s[4][4] = {};
#pragma unroll 8
    for (int kk = 0; kk < 64; kk++) {
      float4 qa = *(const float4*)&Qt[kk * TST + rg];
      float4 kb = *(const float4*)&Kt[kk * TST + cg];
      float av[4] = {qa.x, qa.y, qa.z, qa.w};
      float bv[4] = {kb.x, kb.y, kb.z, kb.w};
#pragma unroll
      for (int ii = 0; ii < 4; ii++)
#pragma unroll
        for (int jj = 0; jj < 4; jj++) s[ii][jj] += av[ii] * bv[jj];
    }

    const float SC = 0.125f;  // 1/sqrt(64)
    if (kt == qt) {
#pragma unroll
      for (int ii = 0; ii < 4; ii++)
#pragma unroll
        for (int jj = 0; jj < 4; jj++)
          s[ii][jj] = (cg + jj > rg + ii) ? -INFINITY : s[ii][jj] * SC;
    } else {
#pragma unroll
      for (int ii = 0; ii < 4; ii++)
#pragma unroll
        for (int jj = 0; jj < 4; jj++) s[ii][jj] *= SC;
    }

    // Online softmax per row (reduce across the 16-lane column group)
#pragma unroll
    for (int ii = 0; ii < 4; ii++) {
      float tmax = fmaxf(fmaxf(s[ii][0], s[ii][1]), fmaxf(s[ii][2], s[ii][3]));
#pragma unroll
      for (int w = 8; w > 0; w >>= 1)
        tmax = fmaxf(tmax, __shfl_xor_sync(0xffffffffu, tmax, w));
      float mn = fmaxf(mrow[ii], tmax);
      float corr = __expf(mrow[ii] - mn);
      float ps = 0.f;
#pragma unroll
      for (int jj = 0; jj < 4; jj++) {
        float pv = __expf(s[ii][jj] - mn);
        s[ii][jj] = pv;
        ps += pv;
      }
#pragma unroll
      for (int w = 8; w > 0; w >>= 1)
        ps += __shfl_xor_sync(0xffffffffu, ps, w);
      lrow[ii] = lrow[ii] * corr + ps;
      mrow[ii] = mn;
#pragma unroll
      for (int jj = 0; jj < 4; jj++) {
        o[ii][jj] *= corr;
        Pt[(cg + jj) * TST + rg + ii] = s[ii][jj];  // transposed P store
      }
    }
    __syncthreads();

    // O += P V  (P transposed in smem: float4 LDS on both operands)
#pragma unroll 8
    for (int c = 0; c < 64; c++) {
      float4 p4 = *(const float4*)&Pt[c * TST + rg];
      float4 v4 = *(const float4*)&Vs[c * TST + cg];
      float pv[4] = {p4.x, p4.y, p4.z, p4.w};
      float vv[4] = {v4.x, v4.y, v4.z, v4.w};
#pragma unroll
      for (int ii = 0; ii < 4; ii++)
#pragma unroll
        for (int jj = 0; jj < 4; jj++) o[ii][jj] += pv[ii] * vv[jj];
    }
    __syncthreads();  // protect Kt/Vs/Pt before next tile's loads
  }

  // Finalize and write [B, S, H*DK]
#pragma unroll
  for (int ii = 0; ii < 4; ii++) {
    float inv = 1.f / lrow[ii];
    float4 r = {o[ii][0] * inv, o[ii][1] * inv, o[ii][2] * inv, o[ii][3] * inv};
    size_t addr = ((size_t)b * SS + qt * 64 + rg + ii) * DD + h * DK + cg;
    *(float4*)(Xo + addr) = r;
  }
}

// ---------------------------------------------------------------------------
// kernel_launch
// Inputs: 0=q, 1=k, 2=v, 3=mask (ignored: tril causal), 4=wq, 5=wk, 6=wv, 7=wo
// ---------------------------------------------------------------------------
extern "C" void kernel_launch(void* const* d_in, const int* in_sizes, int n_in,
                              void* d_out, int out_size) {
  (void)in_sizes; (void)n_in; (void)out_size;
  const float* q = (const float*)d_in[0];
  const float* k = (const float*)d_in[1];
  const float* v = (const float*)d_in[2];
  const float* wq = (const float*)d_in[4];
  const float* wk = (const float*)d_in[5];
  const float* wv = (const float*)d_in[6];
  const float* wo = (const float*)d_in[7];
  float* out = (float*)d_out;

  float *pq, *pk, *pv, *px;
  cudaGetSymbolAddress((void**)&pq, g_q);
  cudaGetSymbolAddress((void**)&pk, g_k);
  cudaGetSymbolAddress((void**)&pv, g_v);
  cudaGetSymbolAddress((void**)&px, g_x);

  dim3 ggrid(8, 32);
  sgemm4096<<<ggrid, 256>>>(q, wq, pq);
  sgemm4096<<<ggrid, 256>>>(k, wk, pk);
  sgemm4096<<<ggrid, 256>>>(v, wv, pv);

  const int pairs = BB * SS * HH * (DK / 2);
  rope_kernel<<<(pairs + 255) / 256, 256>>>(pq, pk);

  cudaFuncSetAttribute(flash_attn, cudaFuncAttributeMaxDynamicSharedMemorySize,
                       ATTN_SMEM);
  flash_attn<<<dim3(BB * HH, SS / 64), 256, ATTN_SMEM>>>(pq, pk, pv, px);

  sgemm4096<<<ggrid, 256>>>(px, wo, out);
}

// round 4
// speedup vs baseline: 1.4692x; 1.4692x over previous
#include <cuda_runtime.h>
#include <cuda_bf16.h>
#include <math.h>

// Problem constants
#define BB 2
#define SS 2048
#define DD 1024
#define HH 16
#define DK 64
#define NROWS (BB * SS)   // 4096

// ---------------------------------------------------------------------------
// Scratch (device globals -- no allocation allowed)
// ---------------------------------------------------------------------------
__device__ float g_q[NROWS * DD];
__device__ float g_k[NROWS * DD];
__device__ float g_v[NROWS * DD];
__device__ float g_x[NROWS * DD];

// ---------------------------------------------------------------------------
// bf16x3 tensor-core GEMM:  Y[n,o] = sum_d X[n,d] * W[o,d]
// fp32 operands split into hi/lo bf16; acc = hi*hi + hi*lo + lo*hi (fp32 acc)
// M=4096, N=1024, K=1024. CTA tile 128x128, K_STEP=32, double buffered.
// 256 threads = 8 warps (2 m-groups x 4 n-groups), warp tile 64x32.
// mma.sync.m16n8k16.row.col bf16, ldmatrix for both operands.
// smem plane stride 40 bf16 (80B rows) -> ldmatrix conflict-free.
// grid = (8, 32)
// ---------------------------------------------------------------------------
#define SA 40
#define PLANE (128 * SA)            // 5120 bf16 elements per plane
#define BUFE (4 * PLANE)            // AHI, ALO, BHI, BLO
#define GEMM_SMEM (2 * BUFE * 2)    // bytes (bf16) = 81920

#define LDSM4(R, addr)                                                   \
  asm volatile(                                                          \
      "ldmatrix.sync.aligned.m8n8.x4.shared.b16 {%0,%1,%2,%3},[%4];"     \
      : "=r"((R)[0]), "=r"((R)[1]), "=r"((R)[2]), "=r"((R)[3])           \
      : "r"(addr))

#define MMA16816(C, A, B0, B1)                                           \
  asm volatile(                                                          \
      "mma.sync.aligned.m16n8k16.row.col.f32.bf16.bf16.f32 "             \
      "{%0,%1,%2,%3},{%4,%5,%6,%7},{%8,%9},{%0,%1,%2,%3};"               \
      : "+f"((C)[0]), "+f"((C)[1]), "+f"((C)[2]), "+f"((C)[3])           \
      : "r"((A)[0]), "r"((A)[1]), "r"((A)[2]), "r"((A)[3]), "r"(B0),     \
        "r"(B1))

__global__ __launch_bounds__(256) void gemm_bf16x3(
    const float* __restrict__ X, const float* __restrict__ W,
    float* __restrict__ Y) {
  extern __shared__ __nv_bfloat16 sb[];
  const unsigned sb32 = (unsigned)__cvta_generic_to_shared(sb);

  const int t = threadIdx.x;
  const int lane = t & 31;
  const int w = t >> 5;
  const int mw = w & 1;    // 0..1 -> m offset mw*64
  const int nw = w >> 1;   // 0..3 -> n offset nw*32
  const int m0 = blockIdx.y * 128;
  const int n0 = blockIdx.x * 128;

  // global staging: each thread owns row (t>>1), k-half (t&1)*16
  const int grow = t >> 1;
  const int gkh = (t & 1) << 4;
  const float* xp = X + (size_t)(m0 + grow) * 1024 + gkh;
  const float* wp = W + (size_t)(n0 + grow) * 1024 + gkh;

  float4 xa[4], xb[4];
#define GLOAD(kt)                                                        \
  do {                                                                   \
    const float* xq = xp + (kt) * 32;                                    \
    const float* wq = wp + (kt) * 32;                                    \
    xa[0] = *(const float4*)(xq);     xa[1] = *(const float4*)(xq + 4);  \
    xa[2] = *(const float4*)(xq + 8); xa[3] = *(const float4*)(xq + 12); \
    xb[0] = *(const float4*)(wq);     xb[1] = *(const float4*)(wq + 4);  \
    xb[2] = *(const float4*)(wq + 8); xb[3] = *(const float4*)(wq + 12); \
  } while (0)

  // convert fp32 -> (hi, lo) bf16 and store to smem buffer `bufi`
#define CSTORE(bufi)                                                     \
  do {                                                                   \
    __nv_bfloat16* base = sb + (bufi) * BUFE;                            \
    __nv_bfloat16* ah = base + grow * SA + gkh;                          \
    __nv_bfloat16* al = ah + PLANE;                                      \
    __nv_bfloat16* bh = ah + 2 * PLANE;                                  \
    __nv_bfloat16* bl = ah + 3 * PLANE;                                  \
    _Pragma("unroll") for (int i = 0; i < 4; i++) {                      \
      float vy[4] = {xa[i].x, xa[i].y, xa[i].z, xa[i].w};                \
      float vz[4] = {xb[i].x, xb[i].y, xb[i].z, xb[i].w};                \
      __nv_bfloat16 h[4], l[4], h2[4], l2[4];                            \
      _Pragma("unroll") for (int j = 0; j < 4; j++) {                    \
        h[j] = __float2bfloat16(vy[j]);                                  \
        l[j] = __float2bfloat16(vy[j] - __bfloat162float(h[j]));         \
        h2[j] = __float2bfloat16(vz[j]);                                 \
        l2[j] = __float2bfloat16(vz[j] - __bfloat162float(h2[j]));       \
      }                                                                  \
      *(__nv_bfloat162*)(ah + i * 4) = __halves2bfloat162(h[0], h[1]);   \
      *(__nv_bfloat162*)(ah + i * 4 + 2) = __halves2bfloat162(h[2], h[3]);\
      *(__nv_bfloat162*)(al + i * 4) = __halves2bfloat162(l[0], l[1]);   \
      *(__nv_bfloat162*)(al + i * 4 + 2) = __halves2bfloat162(l[2], l[3]);\
      *(__nv_bfloat162*)(bh + i * 4) = __halves2bfloat162(h2[0], h2[1]); \
      *(__nv_bfloat162*)(bh + i * 4 + 2) = __halves2bfloat162(h2[2], h2[3]);\
      *(__nv_bfloat162*)(bl + i * 4) = __halves2bfloat162(l2[0], l2[1]); \
      *(__nv_bfloat162*)(bl + i * 4 + 2) = __halves2bfloat162(l2[2], l2[3]);\
    }                                                                    \
  } while (0)

  float acc[4][4][4] = {};

  // ldmatrix lane-address components
  const int a_r = mw * 64 + (lane & 15);
  const int a_c = (lane & 16) ? 8 : 0;
  const int b_r = nw * 32 + (lane & 7) + ((lane & 16) ? 8 : 0);
  const int b_c = (lane & 8) ? 8 : 0;

  GLOAD(0);
  CSTORE(0);
  __syncthreads();

  int buf = 0;
  for (int kt = 0; kt < 32; kt++) {
    if (kt < 31) GLOAD(kt + 1);

    const unsigned bbase = sb32 + buf * (BUFE * 2);
#pragma unroll
    for (int ks = 0; ks < 2; ks++) {
      const int k0 = ks << 4;
      unsigned ahi[4][4], alo[4][4], bhi[2][4], blo[2][4];
      unsigned aaddr = bbase + (unsigned)((a_r * SA + k0 + a_c) << 1);
#pragma unroll
      for (int mf = 0; mf < 4; mf++) {
        LDSM4(ahi[mf], aaddr + mf * (16 * SA * 2));
        LDSM4(alo[mf], aaddr + mf * (16 * SA * 2) + PLANE * 2);
      }
      unsigned baddr =
          bbase + (unsigned)(((2 * PLANE) + b_r * SA + k0 + b_c) << 1);
#pragma unroll
      for (int nf2 = 0; nf2 < 2; nf2++) {
        LDSM4(bhi[nf2], baddr + nf2 * (16 * SA * 2));
        LDSM4(blo[nf2], baddr + nf2 * (16 * SA * 2) + PLANE * 2);
      }
#pragma unroll
      for (int mf = 0; mf < 4; mf++)
#pragma unroll
        for (int nf = 0; nf < 4; nf++) {
          const int g = nf >> 1, hh = (nf & 1) << 1;
          MMA16816(acc[mf][nf], ahi[mf], bhi[g][hh], bhi[g][hh + 1]);
          MMA16816(acc[mf][nf], ahi[mf], blo[g][hh], blo[g][hh + 1]);
          MMA16816(acc[mf][nf], alo[mf], bhi[g][hh], bhi[g][hh + 1]);
        }
    }

    if (kt < 31) {
      CSTORE(buf ^ 1);
      __syncthreads();
      buf ^= 1;
    }
  }
#undef GLOAD
#undef CSTORE

  // Epilogue: c-frag lane mapping (row = lane>>2, col = 2*(lane&3))
  const int erow = m0 + mw * 64 + (lane >> 2);
  const int ecol = n0 + nw * 32 + ((lane & 3) << 1);
#pragma unroll
  for (int mf = 0; mf < 4; mf++)
#pragma unroll
    for (int nf = 0; nf < 4; nf++) {
      float* yp = Y + (size_t)(erow + mf * 16) * 1024 + ecol + nf * 8;
      float2 lo2 = {acc[mf][nf][0], acc[mf][nf][1]};
      float2 hi2 = {acc[mf][nf][2], acc[mf][nf][3]};
      *(float2*)yp = lo2;
      *(float2*)(yp + 8 * 1024) = hi2;
    }
}

// ---------------------------------------------------------------------------
// RoPE (pairwise-interleaved variant, matching the reference exactly)
// ---------------------------------------------------------------------------
__global__ void rope_kernel(float* __restrict__ Q, float* __restrict__ K) {
  const int total = BB * SS * HH * (DK / 2);  // 2,097,152
  int p = blockIdx.x * blockDim.x + threadIdx.x;
  if (p >= total) return;
  const int i = p & 31;                 // pair index within head
  const int s = (p >> 9) & (SS - 1);    // sequence position
  const int m0 = (2 * i) & 31;
  const int m1 = (2 * i + 1) & 31;
  const float L = 0.41524101186091903f;  // log2(10000)/32
  float a0 = (float)s * exp2f(-(float)m0 * L);
  float a1 = (float)s * exp2f(-(float)m1 * L);
  const double INV2PI = 0.15915494309189535;
  const double TWOPI = 6.283185307179586;
  double r0 = (double)a0 - floor((double)a0 * INV2PI) * TWOPI;
  double r1 = (double)a1 - floor((double)a1 * INV2PI) * TWOPI;
  float c0 = cosf((float)r0), s0 = sinf((float)r0);
  float c1 = cosf((float)r1), s1 = sinf((float)r1);

  float2* q2 = (float2*)Q;
  float2* k2 = (float2*)K;
  float2 xq = q2[p];
  float2 xk = k2[p];
  float2 oq, ok;
  oq.x = xq.x * c0 - xq.y * s0;
  oq.y = xq.x * s1 + xq.y * c1;
  ok.x = xk.x * c0 - xk.y * s0;
  ok.y = xk.x * s1 + xk.y * c1;
  q2[p] = oq;
  k2[p] = ok;
}

// ---------------------------------------------------------------------------
// Flash attention, causal, fp32. One CTA = 64 query rows of one (b,h).
// 256 threads, 4x4 register tile; Q/K/P transposed in smem for float4 LDS.
// grid = (B*H=32, S/64=32); qt reversed so long-loop blocks start first.
// ---------------------------------------------------------------------------
#define TST 68
#define ATTN_SMEM (4 * 64 * TST * 4)

__global__ __launch_bounds__(256) void flash_attn(
    const float* __restrict__ Q, const float* __restrict__ K,
    const float* __restrict__ V, float* __restrict__ Xo) {
  extern __shared__ float sm[];
  float* Qt = sm;                  // [dim][qrow]
  float* Kt = sm + 64 * TST;       // [dim][krow]
  float* Vs = sm + 2 * 64 * TST;   // [krow][dim]
  float* Pt = sm + 3 * 64 * TST;   // [kcol][qrow]

  const int t = threadIdx.x;
  const int bh = blockIdx.x;
  const int b = bh >> 4;
  const int h = bh & 15;
  const int qt = (int)gridDim.y - 1 - (int)blockIdx.y;  // heavy blocks first
  const size_t base = (size_t)b * SS * DD + h * DK;

  for (int idx = t; idx < 1024; idx += 256) {
    int rr = idx >> 4;
    int c4 = (idx & 15) << 2;
    float4 v = *(const float4*)(Q + base + (size_t)(qt * 64 + rr) * DD + c4);
    Qt[(c4 + 0) * TST + rr] = v.x;
    Qt[(c4 + 1) * TST + rr] = v.y;
    Qt[(c4 + 2) * TST + rr] = v.z;
    Qt[(c4 + 3) * TST + rr] = v.w;
  }

  const int rg = (t >> 4) << 2;  // this thread's 4 q-rows
  const int cg = (t & 15) << 2;  // this thread's 4 k-cols / v-dims
  float mrow[4] = {-INFINITY, -INFINITY, -INFINITY, -INFINITY};
  float lrow[4] = {0.f, 0.f, 0.f, 0.f};
  float o[4][4] = {};
  __syncthreads();

  for (int kt = 0; kt <= qt; kt++) {
    for (int idx = t; idx < 1024; idx += 256) {
      int rr = idx >> 4;
      int c4 = (idx & 15) << 2;
      size_t g = base + (size_t)(kt * 64 + rr) * DD + c4;
      float4 kv = *(const float4*)(K + g);
      float4 vv = *(const float4*)(V + g);
      Kt[(c4 + 0) * TST + rr] = kv.x;
      Kt[(c4 + 1) * TST + rr] = kv.y;
      Kt[(c4 + 2) * TST + rr] = kv.z;
      Kt[(c4 + 3) * TST + rr] = kv.w;
      float* dv = &Vs[rr * TST + c4];
      dv[0] = vv.x; dv[1] = vv.y; dv[2] = vv.z; dv[3] = vv.w;
    }
    __syncthreads();

    float s[4][4] = {};
#pragma unroll 8
    for (int kk = 0; kk < 64; kk++) {
      float4 qa = *(const float4*)&Qt[kk * TST + rg];
      float4 kb = *(const float4*)&Kt[kk * TST + cg];
      float av[4] = {qa.x, qa.y, qa.z, qa.w};
      float bv[4] = {kb.x, kb.y, kb.z, kb.w};
#pragma unroll
      for (int ii = 0; ii < 4; ii++)
#pragma unroll
        for (int jj = 0; jj < 4; jj++) s[ii][jj] += av[ii] * bv[jj];
    }

    const float SC = 0.125f;  // 1/sqrt(64)
    if (kt == qt) {
#pragma unroll
      for (int ii = 0; ii < 4; ii++)
#pragma unroll
        for (int jj = 0; jj < 4; jj++)
          s[ii][jj] = (cg + jj > rg + ii) ? -INFINITY : s[ii][jj] * SC;
    } else {
#pragma unroll
      for (int ii = 0; ii < 4; ii++)
#pragma unroll
        for (int jj = 0; jj < 4; jj++) s[ii][jj] *= SC;
    }

#pragma unroll
    for (int ii = 0; ii < 4; ii++) {
      float tmax = fmaxf(fmaxf(s[ii][0], s[ii][1]), fmaxf(s[ii][2], s[ii][3]));
#pragma unroll
      for (int w = 8; w > 0; w >>= 1)
        tmax = fmaxf(tmax, __shfl_xor_sync(0xffffffffu, tmax, w));
      float mn = fmaxf(mrow[ii], tmax);
      float corr = __expf(mrow[ii] - mn);
      float ps = 0.f;
#pragma unroll
      for (int jj = 0; jj < 4; jj++) {
        float pv = __expf(s[ii][jj] - mn);
        s[ii][jj] = pv;
        ps += pv;
      }
#pragma unroll
      for (int w = 8; w > 0; w >>= 1)
        ps += __shfl_xor_sync(0xffffffffu, ps, w);
      lrow[ii] = lrow[ii] * corr + ps;
      mrow[ii] = mn;
#pragma unroll
      for (int jj = 0; jj < 4; jj++) {
        o[ii][jj] *= corr;
        Pt[(cg + jj) * TST + rg + ii] = s[ii][jj];
      }
    }
    __syncthreads();

#pragma unroll 8
    for (int c = 0; c < 64; c++) {
      float4 p4 = *(const float4*)&Pt[c * TST + rg];
      float4 v4 = *(const float4*)&Vs[c * TST + cg];
      float pv[4] = {p4.x, p4.y, p4.z, p4.w};
      float vv[4] = {v4.x, v4.y, v4.z, v4.w};
#pragma unroll
      for (int ii = 0; ii < 4; ii++)
#pragma unroll
        for (int jj = 0; jj < 4; jj++) o[ii][jj] += pv[ii] * vv[jj];
    }
    __syncthreads();
  }

#pragma unroll
  for (int ii = 0; ii < 4; ii++) {
    float inv = 1.f / lrow[ii];
    float4 r = {o[ii][0] * inv, o[ii][1] * inv, o[ii][2] * inv, o[ii][3] * inv};
    size_t addr = ((size_t)b * SS + qt * 64 + rg + ii) * DD + h * DK + cg;
    *(float4*)(Xo + addr) = r;
  }
}

// ---------------------------------------------------------------------------
// kernel_launch
// Inputs: 0=q, 1=k, 2=v, 3=mask (ignored: tril causal), 4=wq, 5=wk, 6=wv, 7=wo
// ---------------------------------------------------------------------------
extern "C" void kernel_launch(void* const* d_in, const int* in_sizes, int n_in,
                              void* d_out, int out_size) {
  (void)in_sizes; (void)n_in; (void)out_size;
  const float* q = (const float*)d_in[0];
  const float* k = (const float*)d_in[1];
  const float* v = (const float*)d_in[2];
  const float* wq = (const float*)d_in[4];
  const float* wk = (const float*)d_in[5];
  const float* wv = (const float*)d_in[6];
  const float* wo = (const float*)d_in[7];
  float* out = (float*)d_out;

  float *pq, *pk, *pv, *px;
  cudaGetSymbolAddress((void**)&pq, g_q);
  cudaGetSymbolAddress((void**)&pk, g_k);
  cudaGetSymbolAddress((void**)&pv, g_v);
  cudaGetSymbolAddress((void**)&px, g_x);

  cudaFuncSetAttribute(gemm_bf16x3, cudaFuncAttributeMaxDynamicSharedMemorySize,
                       GEMM_SMEM);
  cudaFuncSetAttribute(flash_attn, cudaFuncAttributeMaxDynamicSharedMemorySize,
                       ATTN_SMEM);

  dim3 ggrid(8, 32);
  gemm_bf16x3<<<ggrid, 256, GEMM_SMEM>>>(q, wq, pq);
  gemm_bf16x3<<<ggrid, 256, GEMM_SMEM>>>(k, wk, pk);
  gemm_bf16x3<<<ggrid, 256, GEMM_SMEM>>>(v, wv, pv);

  const int pairs = BB * SS * HH * (DK / 2);
  rope_kernel<<<(pairs + 255) / 256, 256>>>(pq, pk);

  flash_attn<<<dim3(BB * HH, SS / 64), 256, ATTN_SMEM>>>(pq, pk, pv, px);

  gemm_bf16x3<<<ggrid, 256, GEMM_SMEM>>>(px, wo, out);
}

// round 7
// speedup vs baseline: 2.2646x; 1.5414x over previous
#include <cuda_runtime.h>
#include <cuda_bf16.h>
#include <math.h>

// Problem constants
#define BB 2
#define SS 2048
#define DD 1024
#define HH 16
#define DK 64
#define NROWS (BB * SS)   // 4096
#define NEL (NROWS * DD)  // 4M
#define WEL (DD * DD)     // 1M

// ---------------------------------------------------------------------------
// Scratch (device globals -- no allocation allowed)
// ---------------------------------------------------------------------------
__device__ float g_q[NEL];
__device__ float g_k[NEL];
__device__ float g_v[NEL];
__device__ float g_x[NEL];
// bf16 hi/lo planes. The 6 input planes are reused post-projection for the
// rope'd q/k and split v (stream order makes this safe).
__device__ __nv_bfloat16 g_qh[NEL], g_ql[NEL];
__device__ __nv_bfloat16 g_kh[NEL], g_kl[NEL];
__device__ __nv_bfloat16 g_vh[NEL], g_vl[NEL];
__device__ __nv_bfloat16 g_xh[NEL], g_xl[NEL];
__device__ __nv_bfloat16 g_wqh[WEL], g_wql[WEL];
__device__ __nv_bfloat16 g_wkh[WEL], g_wkl[WEL];
__device__ __nv_bfloat16 g_wvh[WEL], g_wvl[WEL];
__device__ __nv_bfloat16 g_woh[WEL], g_wol[WEL];

// ---------------------------------------------------------------------------
// MMA / LDSM primitives
// ---------------------------------------------------------------------------
#define LDSM4(R, addr)                                                   \
  asm volatile(                                                          \
      "ldmatrix.sync.aligned.m8n8.x4.shared.b16 {%0,%1,%2,%3},[%4];"     \
      : "=r"((R)[0]), "=r"((R)[1]), "=r"((R)[2]), "=r"((R)[3])           \
      : "r"(addr))

#define LDSM4T(R, addr)                                                  \
  asm volatile(                                                          \
      "ldmatrix.sync.aligned.m8n8.x4.trans.shared.b16 {%0,%1,%2,%3},[%4];" \
      : "=r"((R)[0]), "=r"((R)[1]), "=r"((R)[2]), "=r"((R)[3])           \
      : "r"(addr))

#define MMA16816(C, A, B0, B1)                                           \
  asm volatile(                                                          \
      "mma.sync.aligned.m16n8k16.row.col.f32.bf16.bf16.f32 "             \
      "{%0,%1,%2,%3},{%4,%5,%6,%7},{%8,%9},{%0,%1,%2,%3};"               \
      : "+f"((C)[0]), "+f"((C)[1]), "+f"((C)[2]), "+f"((C)[3])           \
      : "r"((A)[0]), "r"((A)[1]), "r"((A)[2]), "r"((A)[3]), "r"(B0),     \
        "r"(B1))

__device__ __forceinline__ unsigned pack_bf16(float a, float b) {
  __nv_bfloat162 t = __halves2bfloat162(__float2bfloat16(a), __float2bfloat16(b));
  return *(unsigned*)&t;
}

// ---------------------------------------------------------------------------
// split: fp32 -> (hi, lo) bf16 planes
// ---------------------------------------------------------------------------
__global__ void split_kernel(const float* __restrict__ x,
                             __nv_bfloat16* __restrict__ hi,
                             __nv_bfloat16* __restrict__ lo, int n) {
  int i = (blockIdx.x * blockDim.x + threadIdx.x) << 2;
  if (i >= n) return;
  float4 v = *(const float4*)(x + i);
  float f[4] = {v.x, v.y, v.z, v.w};
  __nv_bfloat16 h[4], l[4];
#pragma unroll
  for (int j = 0; j < 4; j++) {
    h[j] = __float2bfloat16(f[j]);
    l[j] = __float2bfloat16(f[j] - __bfloat162float(h[j]));
  }
  *(__nv_bfloat162*)(hi + i) = __halves2bfloat162(h[0], h[1]);
  *(__nv_bfloat162*)(hi + i + 2) = __halves2bfloat162(h[2], h[3]);
  *(__nv_bfloat162*)(lo + i) = __halves2bfloat162(l[0], l[1]);
  *(__nv_bfloat162*)(lo + i + 2) = __halves2bfloat162(l[2], l[3]);
}

// ---------------------------------------------------------------------------
// bf16-plane tensor-core GEMM: Y[n,o] = sum_d X[n,d] * W[o,d]
// acc = hi*hi + hi*lo + lo*hi (fp32 acc). M=4096,N=1024,K=1024.
// CTA 128x128, K_STEP 32, double buffered, 8 warps (2m x 4n), warp 64x32.
// grid = (8, 32)
// ---------------------------------------------------------------------------
#define SA 40
#define PLANE (128 * SA)            // 5120 bf16 per plane
#define BUFE (4 * PLANE)            // AHI, ALO, BHI, BLO
#define GEMM_SMEM (2 * BUFE * 2)    // 81920 bytes

__global__ __launch_bounds__(256) void gemm_planes(
    const __nv_bfloat16* __restrict__ Xh, const __nv_bfloat16* __restrict__ Xl,
    const __nv_bfloat16* __restrict__ Wh, const __nv_bfloat16* __restrict__ Wl,
    float* __restrict__ Y) {
  extern __shared__ __nv_bfloat16 sb[];
  const unsigned sb32 = (unsigned)__cvta_generic_to_shared(sb);

  const int t = threadIdx.x;
  const int lane = t & 31;
  const int w = t >> 5;
  const int mw = w & 1;
  const int nw = w >> 1;
  const int m0 = blockIdx.y * 128;
  const int n0 = blockIdx.x * 128;

  const int grow = t >> 1;
  const int gkh = (t & 1) << 4;
  const __nv_bfloat16* xh = Xh + (size_t)(m0 + grow) * 1024 + gkh;
  const __nv_bfloat16* xl = Xl + (size_t)(m0 + grow) * 1024 + gkh;
  const __nv_bfloat16* wh = Wh + (size_t)(n0 + grow) * 1024 + gkh;
  const __nv_bfloat16* wl = Wl + (size_t)(n0 + grow) * 1024 + gkh;

  uint4 rah0, rah1, ral0, ral1, rbh0, rbh1, rbl0, rbl1;
#define GLOAD(kt)                                                        \
  do {                                                                   \
    int o_ = (kt) * 32;                                                  \
    rah0 = *(const uint4*)(xh + o_);  rah1 = *(const uint4*)(xh + o_ + 8); \
    ral0 = *(const uint4*)(xl + o_);  ral1 = *(const uint4*)(xl + o_ + 8); \
    rbh0 = *(const uint4*)(wh + o_);  rbh1 = *(const uint4*)(wh + o_ + 8); \
    rbl0 = *(const uint4*)(wl + o_);  rbl1 = *(const uint4*)(wl + o_ + 8); \
  } while (0)

#define SSTORE(bufi)                                                     \
  do {                                                                   \
    __nv_bfloat16* p_ = sb + (bufi) * BUFE + grow * SA + gkh;            \
    *(uint4*)(p_) = rah0;              *(uint4*)(p_ + 8) = rah1;         \
    *(uint4*)(p_ + PLANE) = ral0;      *(uint4*)(p_ + PLANE + 8) = ral1; \
    *(uint4*)(p_ + 2 * PLANE) = rbh0;  *(uint4*)(p_ + 2 * PLANE + 8) = rbh1; \
    *(uint4*)(p_ + 3 * PLANE) = rbl0;  *(uint4*)(p_ + 3 * PLANE + 8) = rbl1; \
  } while (0)

  float acc[4][4][4] = {};

  const int a_r = mw * 64 + (lane & 15);
  const int a_c = (lane & 16) ? 8 : 0;
  const int b_r = nw * 32 + (lane & 7) + ((lane & 16) ? 8 : 0);
  const int b_c = (lane & 8) ? 8 : 0;

  GLOAD(0);
  SSTORE(0);
  __syncthreads();

  int buf = 0;
  for (int kt = 0; kt < 32; kt++) {
    if (kt < 31) GLOAD(kt + 1);

    const unsigned bbase = sb32 + buf * (BUFE * 2);
#pragma unroll
    for (int ks = 0; ks < 2; ks++) {
      const int k0 = ks << 4;
      unsigned ahi[4][4], alo[4][4], bhi[2][4], blo[2][4];
      unsigned aaddr = bbase + (unsigned)((a_r * SA + k0 + a_c) << 1);
#pragma unroll
      for (int mf = 0; mf < 4; mf++) {
        LDSM4(ahi[mf], aaddr + mf * (16 * SA * 2));
        LDSM4(alo[mf], aaddr + mf * (16 * SA * 2) + PLANE * 2);
      }
      unsigned baddr =
          bbase + (unsigned)(((2 * PLANE) + b_r * SA + k0 + b_c) << 1);
#pragma unroll
      for (int nf2 = 0; nf2 < 2; nf2++) {
        LDSM4(bhi[nf2], baddr + nf2 * (16 * SA * 2));
        LDSM4(blo[nf2], baddr + nf2 * (16 * SA * 2) + PLANE * 2);
      }
#pragma unroll
      for (int mf = 0; mf < 4; mf++)
#pragma unroll
        for (int nf = 0; nf < 4; nf++) {
          const int g = nf >> 1, hh = (nf & 1) << 1;
          MMA16816(acc[mf][nf], ahi[mf], bhi[g][hh], bhi[g][hh + 1]);
          MMA16816(acc[mf][nf], ahi[mf], blo[g][hh], blo[g][hh + 1]);
          MMA16816(acc[mf][nf], alo[mf], bhi[g][hh], bhi[g][hh + 1]);
        }
    }

    if (kt < 31) {
      SSTORE(buf ^ 1);
      __syncthreads();
      buf ^= 1;
    }
  }
#undef GLOAD
#undef SSTORE

  const int erow = m0 + mw * 64 + (lane >> 2);
  const int ecol = n0 + nw * 32 + ((lane & 3) << 1);
#pragma unroll
  for (int mf = 0; mf < 4; mf++)
#pragma unroll
    for (int nf = 0; nf < 4; nf++) {
      float* yp = Y + (size_t)(erow + mf * 16) * 1024 + ecol + nf * 8;
      float2 lo2 = {acc[mf][nf][0], acc[mf][nf][1]};
      float2 hi2 = {acc[mf][nf][2], acc[mf][nf][3]};
      *(float2*)yp = lo2;
      *(float2*)(yp + 8 * 1024) = hi2;
    }
}

// ---------------------------------------------------------------------------
// RoPE + split: fp32 q/k (proj out) -> rotated bf16 hi/lo planes.
// Pairwise-interleaved variant, fp32 angle + double range reduction.
// ---------------------------------------------------------------------------
__global__ void rope_split_kernel(
    const float* __restrict__ Qf, const float* __restrict__ Kf,
    __nv_bfloat16* __restrict__ qh, __nv_bfloat16* __restrict__ ql,
    __nv_bfloat16* __restrict__ kh, __nv_bfloat16* __restrict__ kl) {
  const int total = BB * SS * HH * (DK / 2);
  int p = blockIdx.x * blockDim.x + threadIdx.x;
  if (p >= total) return;
  const int i = p & 31;
  const int s = (p >> 9) & (SS - 1);
  const int m0 = (2 * i) & 31;
  const int m1 = (2 * i + 1) & 31;
  const float L = 0.41524101186091903f;  // log2(10000)/32
  float a0 = (float)s * exp2f(-(float)m0 * L);
  float a1 = (float)s * exp2f(-(float)m1 * L);
  const double INV2PI = 0.15915494309189535;
  const double TWOPI = 6.283185307179586;
  double r0 = (double)a0 - floor((double)a0 * INV2PI) * TWOPI;
  double r1 = (double)a1 - floor((double)a1 * INV2PI) * TWOPI;
  float c0 = cosf((float)r0), s0 = sinf((float)r0);
  float c1 = cosf((float)r1), s1 = sinf((float)r1);

  float2 xq = ((const float2*)Qf)[p];
  float2 xk = ((const float2*)Kf)[p];
  float oq0 = xq.x * c0 - xq.y * s0;
  float oq1 = xq.x * s1 + xq.y * c1;
  float ok0 = xk.x * c0 - xk.y * s0;
  float ok1 = xk.x * s1 + xk.y * c1;

  __nv_bfloat16 qh0 = __float2bfloat16(oq0), qh1 = __float2bfloat16(oq1);
  __nv_bfloat16 kh0 = __float2bfloat16(ok0), kh1 = __float2bfloat16(ok1);
  *(__nv_bfloat162*)(qh + 2 * p) = __halves2bfloat162(qh0, qh1);
  *(__nv_bfloat162*)(ql + 2 * p) = __halves2bfloat162(
      __float2bfloat16(oq0 - __bfloat162float(qh0)),
      __float2bfloat16(oq1 - __bfloat162float(qh1)));
  *(__nv_bfloat162*)(kh + 2 * p) = __halves2bfloat162(kh0, kh1);
  *(__nv_bfloat162*)(kl + 2 * p) = __halves2bfloat162(
      __float2bfloat16(ok0 - __bfloat162float(kh0)),
      __float2bfloat16(ok1 - __bfloat162float(kh1)));
}

// ---------------------------------------------------------------------------
// MMA flash attention (causal, bf16x3, fp32 softmax/acc).
// CTA = 64 q-rows of one (b,h), 128 threads, warp wi owns rows [16wi,16wi+16).
// Q held in registers as A-frags; K via ldsm ([n][k]); V via ldsm.trans ([k][d]).
// P repacked c-frag -> A-frag in registers. grid (B*H=32, 32), qt reversed.
// ---------------------------------------------------------------------------
#define AST 72
#define ATTN_SMEM (4 * 64 * AST * 2)  // 36864 B

__global__ __launch_bounds__(128) void attn_mma(
    const __nv_bfloat16* __restrict__ Qh, const __nv_bfloat16* __restrict__ Ql,
    const __nv_bfloat16* __restrict__ Kh, const __nv_bfloat16* __restrict__ Kl,
    const __nv_bfloat16* __restrict__ Vh, const __nv_bfloat16* __restrict__ Vl,
    float* __restrict__ Xo) {
  extern __shared__ __nv_bfloat16 as_[];
  __nv_bfloat16* kh = as_;                 // K hi (staging also used for Q hi)
  __nv_bfloat16* kl = as_ + 64 * AST;      // K lo
  __nv_bfloat16* vh = as_ + 2 * 64 * AST;  // V hi
  __nv_bfloat16* vl = as_ + 3 * 64 * AST;  // V lo
  const unsigned s_kh = (unsigned)__cvta_generic_to_shared(kh);
  const unsigned s_vh = (unsigned)__cvta_generic_to_shared(vh);
  const unsigned PL2 = 64 * AST * 2;       // byte offset hi->lo plane

  const int t = threadIdx.x;
  const int lane = t & 31;
  const int wi = t >> 5;
  const int b = blockIdx.x >> 4;
  const int h = blockIdx.x & 15;
  const int qt = (int)gridDim.y - 1 - (int)blockIdx.y;
  const size_t base = (size_t)b * SS * DD + h * DK;

  // ---- stage Q tile through kh/kl, pull A-frags into registers ----
  for (int idx = t; idx < 512; idx += 128) {
    int r = idx >> 3, c = (idx & 7) << 3;
    size_t g = base + (size_t)(qt * 64 + r) * DD + c;
    *(uint4*)&kh[r * AST + c] = *(const uint4*)&Qh[g];
    *(uint4*)&kl[r * AST + c] = *(const uint4*)&Ql[g];
  }
  __syncthreads();
  const int a_r = wi * 16 + (lane & 15);
  const int a_c = (lane & 16) ? 8 : 0;
  unsigned qfh[4][4], qfl[4][4];
#pragma unroll
  for (int kc = 0; kc < 4; kc++) {
    unsigned ad = s_kh + (unsigned)((a_r * AST + kc * 16 + a_c) << 1);
    LDSM4(qfh[kc], ad);
    LDSM4(qfl[kc], ad + PL2);
  }
  __syncthreads();

  const int b_r = (lane & 7) + ((lane & 16) ? 8 : 0);
  const int b_c = (lane & 8) ? 8 : 0;
  const int v_r = lane & 15;
  const int v_c = ((lane >> 4) & 1) << 3;

  float o[8][4] = {};
  float mrow[2] = {-INFINITY, -INFINITY};
  float lrow[2] = {0.f, 0.f};
  const int grow0 = qt * 64 + wi * 16 + (lane >> 2);
  const int gcol0 = (lane & 3) << 1;

  for (int j = 0; j <= qt; j++) {
    // ---- load K/V tiles ----
    for (int idx = t; idx < 512; idx += 128) {
      int r = idx >> 3, c = (idx & 7) << 3;
      size_t g = base + (size_t)(j * 64 + r) * DD + c;
      *(uint4*)&kh[r * AST + c] = *(const uint4*)&Kh[g];
      *(uint4*)&kl[r * AST + c] = *(const uint4*)&Kl[g];
      *(uint4*)&vh[r * AST + c] = *(const uint4*)&Vh[g];
      *(uint4*)&vl[r * AST + c] = *(const uint4*)&Vl[g];
    }
    __syncthreads();

    // ---- S = Q K^T  (bf16x3) ----
    float sc[8][4] = {};
#pragma unroll
    for (int kc = 0; kc < 4; kc++) {
      unsigned bh[4][4], bl[4][4];
#pragma unroll
      for (int g2 = 0; g2 < 4; g2++) {
        unsigned ad =
            s_kh + (unsigned)(((g2 * 16 + b_r) * AST + kc * 16 + b_c) << 1);
        LDSM4(bh[g2], ad);
        LDSM4(bl[g2], ad + PL2);
      }
#pragma unroll
      for (int nf = 0; nf < 8; nf++) {
        const int g2 = nf >> 1, hh = (nf & 1) << 1;
        MMA16816(sc[nf], qfh[kc], bh[g2][hh], bh[g2][hh + 1]);
        MMA16816(sc[nf], qfh[kc], bl[g2][hh], bl[g2][hh + 1]);
        MMA16816(sc[nf], qfl[kc], bh[g2][hh], bh[g2][hh + 1]);
      }
    }

    // ---- scale + causal mask ----
    const float SC = 0.125f;  // 1/sqrt(64)
    if (j == qt) {
#pragma unroll
      for (int nf = 0; nf < 8; nf++)
#pragma unroll
        for (int e = 0; e < 4; e++) {
          int col = j * 64 + nf * 8 + gcol0 + (e & 1);
          int row = grow0 + ((e >> 1) << 3);
          sc[nf][e] = (col > row) ? -INFINITY : sc[nf][e] * SC;
        }
    } else {
#pragma unroll
      for (int nf = 0; nf < 8; nf++)
#pragma unroll
        for (int e = 0; e < 4; e++) sc[nf][e] *= SC;
    }

    // ---- online softmax (rows r, r+8; reduce over 4-lane row group) ----
#pragma unroll
    for (int i = 0; i < 2; i++) {
      float tm = -INFINITY;
#pragma unroll
      for (int nf = 0; nf < 8; nf++)
        tm = fmaxf(tm, fmaxf(sc[nf][2 * i], sc[nf][2 * i + 1]));
      tm = fmaxf(tm, __shfl_xor_sync(0xffffffffu, tm, 1));
      tm = fmaxf(tm, __shfl_xor_sync(0xffffffffu, tm, 2));
      float mn = fmaxf(mrow[i], tm);
      float corr = __expf(mrow[i] - mn);
      float ps = 0.f;
#pragma unroll
      for (int nf = 0; nf < 8; nf++) {
        float p0 = __expf(sc[nf][2 * i] - mn);
        float p1 = __expf(sc[nf][2 * i + 1] - mn);
        sc[nf][2 * i] = p0;
        sc[nf][2 * i + 1] = p1;
        ps += p0 + p1;
      }
      ps += __shfl_xor_sync(0xffffffffu, ps, 1);
      ps += __shfl_xor_sync(0xffffffffu, ps, 2);
      lrow[i] = lrow[i] * corr + ps;
      mrow[i] = mn;
#pragma unroll
      for (int nf = 0; nf < 8; nf++) {
        o[nf][2 * i] *= corr;
        o[nf][2 * i + 1] *= corr;
      }
    }

    // ---- O += P V  (P from registers, V via ldsm.trans, bf16x3) ----
#pragma unroll
    for (int kc = 0; kc < 4; kc++) {
      unsigned pa[4], pl[4];
#pragma unroll
      for (int rr = 0; rr < 2; rr++) {
        float f0 = sc[2 * kc + rr][0], f1 = sc[2 * kc + rr][1];
        float f2 = sc[2 * kc + rr][2], f3 = sc[2 * kc + rr][3];
        __nv_bfloat16 h0 = __float2bfloat16(f0), h1 = __float2bfloat16(f1);
        __nv_bfloat16 h2 = __float2bfloat16(f2), h3 = __float2bfloat16(f3);
        pa[2 * rr] = pack_bf16(f0, f1);
        pa[2 * rr + 1] = pack_bf16(f2, f3);
        pl[2 * rr] = pack_bf16(f0 - __bfloat162float(h0),
                               f1 - __bfloat162float(h1));
        pl[2 * rr + 1] = pack_bf16(f2 - __bfloat162float(h2),
                                   f3 - __bfloat162float(h3));
      }
      unsigned wvh[4][4], wvl[4][4];
#pragma unroll
      for (int g2 = 0; g2 < 4; g2++) {
        unsigned ad =
            s_vh + (unsigned)(((kc * 16 + v_r) * AST + g2 * 16 + v_c) << 1);
        LDSM4T(wvh[g2], ad);
        LDSM4T(wvl[g2], ad + PL2);
      }
#pragma unroll
      for (int nf = 0; nf < 8; nf++) {
        const int g2 = nf >> 1, hh = (nf & 1) << 1;
        MMA16816(o[nf], pa, wvh[g2][hh], wvh[g2][hh + 1]);
        MMA16816(o[nf], pa, wvl[g2][hh], wvl[g2][hh + 1]);
        MMA16816(o[nf], pl, wvh[g2][hh], wvh[g2][hh + 1]);
      }
    }
    __syncthreads();
  }

  // ---- finalize ----
#pragma unroll
  for (int i = 0; i < 2; i++) {
    float inv = 1.f / lrow[i];
    int row = grow0 + i * 8;
#pragma unroll
    for (int nf = 0; nf < 8; nf++) {
      float2 r2 = {o[nf][2 * i] * inv, o[nf][2 * i + 1] * inv};
      *(float2*)&Xo[(size_t)(b * SS + row) * DD + h * DK + nf * 8 + gcol0] = r2;
    }
  }
}

// ---------------------------------------------------------------------------
// kernel_launch
// Inputs: 0=q, 1=k, 2=v, 3=mask (ignored: tril causal), 4=wq, 5=wk, 6=wv, 7=wo
// ---------------------------------------------------------------------------
extern "C" void kernel_launch(void* const* d_in, const int* in_sizes, int n_in,
                              void* d_out, int out_size) {
  (void)in_sizes; (void)n_in; (void)out_size;
  const float* q = (const float*)d_in[0];
  const float* k = (const float*)d_in[1];
  const float* v = (const float*)d_in[2];
  const float* wq = (const float*)d_in[4];
  const float* wk = (const float*)d_in[5];
  const float* wv = (const float*)d_in[6];
  const float* wo = (const float*)d_in[7];
  float* out = (float*)d_out;

  float *pq, *pk, *pv, *px;
  cudaGetSymbolAddress((void**)&pq, g_q);
  cudaGetSymbolAddress((void**)&pk, g_k);
  cudaGetSymbolAddress((void**)&pv, g_v);
  cudaGetSymbolAddress((void**)&px, g_x);
  __nv_bfloat16 *qh, *ql, *kh, *kl, *vh, *vl, *xh, *xl;
  cudaGetSymbolAddress((void**)&qh, g_qh); cudaGetSymbolAddress((void**)&ql, g_ql);
  cudaGetSymbolAddress((void**)&kh, g_kh); cudaGetSymbolAddress((void**)&kl, g_kl);
  cudaGetSymbolAddress((void**)&vh, g_vh); cudaGetSymbolAddress((void**)&vl, g_vl);
  cudaGetSymbolAddress((void**)&xh, g_xh); cudaGetSymbolAddress((void**)&xl, g_xl);
  __nv_bfloat16 *wqh, *wql, *wkh, *wkl, *wvh, *wvl, *woh, *wol;
  cudaGetSymbolAddress((void**)&wqh, g_wqh); cudaGetSymbolAddress((void**)&wql, g_wql);
  cudaGetSymbolAddress((void**)&wkh, g_wkh); cudaGetSymbolAddress((void**)&wkl, g_wkl);
  cudaGetSymbolAddress((void**)&wvh, g_wvh); cudaGetSymbolAddress((void**)&wvl, g_wvl);
  cudaGetSymbolAddress((void**)&woh, g_woh); cudaGetSymbolAddress((void**)&wol, g_wol);

  cudaFuncSetAttribute(gemm_planes, cudaFuncAttributeMaxDynamicSharedMemorySize,
                       GEMM_SMEM);
  cudaFuncSetAttribute(attn_mma, cudaFuncAttributeMaxDynamicSharedMemorySize,
                       ATTN_SMEM);

  // split inputs + weights
  split_kernel<<<NEL / 1024, 256>>>(q, qh, ql, NEL);
  split_kernel<<<NEL / 1024, 256>>>(k, kh, kl, NEL);
  split_kernel<<<NEL / 1024, 256>>>(v, vh, vl, NEL);
  split_kernel<<<WEL / 1024, 256>>>(wq, wqh, wql, WEL);
  split_kernel<<<WEL / 1024, 256>>>(wk, wkh, wkl, WEL);
  split_kernel<<<WEL / 1024, 256>>>(wv, wvh, wvl, WEL);
  split_kernel<<<WEL / 1024, 256>>>(wo, woh, wol, WEL);

  // projections
  dim3 ggrid(8, 32);
  gemm_planes<<<ggrid, 256, GEMM_SMEM>>>(qh, ql, wqh, wql, pq);
  gemm_planes<<<ggrid, 256, GEMM_SMEM>>>(kh, kl, wkh, wkl, pk);
  gemm_planes<<<ggrid, 256, GEMM_SMEM>>>(vh, vl, wvh, wvl, pv);

  // rope + re-split (reuse input planes), v split
  const int pairs = BB * SS * HH * (DK / 2);
  rope_split_kernel<<<pairs / 256, 256>>>(pq, pk, qh, ql, kh, kl);
  split_kernel<<<NEL / 1024, 256>>>(pv, vh, vl, NEL);

  // attention
  attn_mma<<<dim3(BB * HH, SS / 64), 128, ATTN_SMEM>>>(qh, ql, kh, kl, vh, vl,
                                                       px);

  // output projection
  split_kernel<<<NEL / 1024, 256>>>(px, xh, xl, NEL);
  gemm_planes<<<ggrid, 256, GEMM_SMEM>>>(xh, xl, woh, wol, out);
}

// round 9
// speedup vs baseline: 2.4240x; 1.0704x over previous
#include <cuda_runtime.h>
#include <cuda_bf16.h>
#include <math.h>

// Problem constants
#define BB 2
#define SS 2048
#define DD 1024
#define HH 16
#define DK 64
#define NROWS (BB * SS)   // 4096
#define NEL (NROWS * DD)  // 4M
#define WEL (DD * DD)     // 1M

// ---------------------------------------------------------------------------
// Scratch (device globals -- no allocation allowed)
// ---------------------------------------------------------------------------
__device__ float g_q[NEL];
__device__ float g_k[NEL];
// hi/lo bf16 planes
__device__ __nv_bfloat16 g_qh[NEL], g_ql[NEL];   // input q -> rope'd q
__device__ __nv_bfloat16 g_kh[NEL], g_kl[NEL];   // input k -> rope'd k
__device__ __nv_bfloat16 g_vh[NEL], g_vl[NEL];   // input v
__device__ __nv_bfloat16 g_xh[NEL], g_xl[NEL];   // projected V planes
__device__ __nv_bfloat16 g_yh[NEL], g_yl[NEL];   // attention output planes
__device__ __nv_bfloat16 g_wqh[WEL], g_wql[WEL];
__device__ __nv_bfloat16 g_wkh[WEL], g_wkl[WEL];
__device__ __nv_bfloat16 g_wvh[WEL], g_wvl[WEL];
__device__ __nv_bfloat16 g_woh[WEL], g_wol[WEL];

// ---------------------------------------------------------------------------
// Primitives
// ---------------------------------------------------------------------------
#define LDSM4(R, addr)                                                   \
  asm volatile(                                                          \
      "ldmatrix.sync.aligned.m8n8.x4.shared.b16 {%0,%1,%2,%3},[%4];"     \
      : "=r"((R)[0]), "=r"((R)[1]), "=r"((R)[2]), "=r"((R)[3])           \
      : "r"(addr))

#define LDSM4T(R, addr)                                                  \
  asm volatile(                                                          \
      "ldmatrix.sync.aligned.m8n8.x4.trans.shared.b16 {%0,%1,%2,%3},[%4];" \
      : "=r"((R)[0]), "=r"((R)[1]), "=r"((R)[2]), "=r"((R)[3])           \
      : "r"(addr))

#define MMA16816(C, A, B0, B1)                                           \
  asm volatile(                                                          \
      "mma.sync.aligned.m16n8k16.row.col.f32.bf16.bf16.f32 "             \
      "{%0,%1,%2,%3},{%4,%5,%6,%7},{%8,%9},{%0,%1,%2,%3};"               \
      : "+f"((C)[0]), "+f"((C)[1]), "+f"((C)[2]), "+f"((C)[3])           \
      : "r"((A)[0]), "r"((A)[1]), "r"((A)[2]), "r"((A)[3]), "r"(B0),     \
        "r"(B1))

#define CPA16(dst, src)                                                  \
  asm volatile("cp.async.cg.shared.global [%0], [%1], 16;" ::"r"(dst),   \
               "l"(src))
#define CPA_COMMIT() asm volatile("cp.async.commit_group;" ::)
#define CPA_WAIT(n) asm volatile("cp.async.wait_group %0;" ::"n"(n))

__device__ __forceinline__ unsigned pack_bf16(float a, float b) {
  __nv_bfloat162 t = __halves2bfloat162(__float2bfloat16(a), __float2bfloat16(b));
  return *(unsigned*)&t;
}

// ---------------------------------------------------------------------------
// split: fp32 -> (hi, lo) bf16 planes
// ---------------------------------------------------------------------------
__global__ void split_kernel(const float* __restrict__ x,
                             __nv_bfloat16* __restrict__ hi,
                             __nv_bfloat16* __restrict__ lo, int n) {
  int i = (blockIdx.x * blockDim.x + threadIdx.x) << 2;
  if (i >= n) return;
  float4 v = *(const float4*)(x + i);
  float f[4] = {v.x, v.y, v.z, v.w};
  __nv_bfloat16 h[4], l[4];
#pragma unroll
  for (int j = 0; j < 4; j++) {
    h[j] = __float2bfloat16(f[j]);
    l[j] = __float2bfloat16(f[j] - __bfloat162float(h[j]));
  }
  *(__nv_bfloat162*)(hi + i) = __halves2bfloat162(h[0], h[1]);
  *(__nv_bfloat162*)(hi + i + 2) = __halves2bfloat162(h[2], h[3]);
  *(__nv_bfloat162*)(lo + i) = __halves2bfloat162(l[0], l[1]);
  *(__nv_bfloat162*)(lo + i + 2) = __halves2bfloat162(l[2], l[3]);
}

// ---------------------------------------------------------------------------
// bf16-plane tensor-core GEMM (cp.async 2-stage):
// Y[n,o] = sum_d X[n,d]*W[o,d]; acc = hi*hi + hi*lo + lo*hi.
// CTA 128x128, K_STEP 32, 8 warps (2m x 4n), warp 64x32. grid (8, 32).
// EPI=0: fp32 output. EPI=1: bf16 hi/lo plane output.
// ---------------------------------------------------------------------------
#define SA 40
#define PLANE (128 * SA)            // 5120 bf16 per plane
#define BUFE (4 * PLANE)            // AHI, ALO, BHI, BLO
#define GEMM_SMEM (2 * BUFE * 2)    // 81920 bytes

template <int EPI>
__global__ __launch_bounds__(256) void gemm_cpa(
    const __nv_bfloat16* __restrict__ Xh, const __nv_bfloat16* __restrict__ Xl,
    const __nv_bfloat16* __restrict__ Wh, const __nv_bfloat16* __restrict__ Wl,
    float* __restrict__ Y, __nv_bfloat16* __restrict__ Yh,
    __nv_bfloat16* __restrict__ Yl) {
  extern __shared__ __nv_bfloat16 sb[];
  const unsigned sb32 = (unsigned)__cvta_generic_to_shared(sb);

  const int t = threadIdx.x;
  const int lane = t & 31;
  const int w = t >> 5;
  const int mw = w & 1;
  const int nw = w >> 1;
  const int m0 = blockIdx.y * 128;
  const int n0 = blockIdx.x * 128;

  const int grow = t >> 1;
  const int gkh = (t & 1) << 4;
  const __nv_bfloat16* xh = Xh + (size_t)(m0 + grow) * 1024 + gkh;
  const __nv_bfloat16* xl = Xl + (size_t)(m0 + grow) * 1024 + gkh;
  const __nv_bfloat16* wh = Wh + (size_t)(n0 + grow) * 1024 + gkh;
  const __nv_bfloat16* wl = Wl + (size_t)(n0 + grow) * 1024 + gkh;
  const unsigned sdst = sb32 + (unsigned)((grow * SA + gkh) << 1);

  auto issue = [&](int kt, int bufi) {
    const unsigned d = sdst + (unsigned)(bufi * (BUFE * 2));
    const int o_ = kt * 32;
    CPA16(d, xh + o_);
    CPA16(d + 16, xh + o_ + 8);
    CPA16(d + PLANE * 2, xl + o_);
    CPA16(d + PLANE * 2 + 16, xl + o_ + 8);
    CPA16(d + 2 * PLANE * 2, wh + o_);
    CPA16(d + 2 * PLANE * 2 + 16, wh + o_ + 8);
    CPA16(d + 3 * PLANE * 2, wl + o_);
    CPA16(d + 3 * PLANE * 2 + 16, wl + o_ + 8);
    CPA_COMMIT();
  };

  float acc[4][4][4] = {};

  const int a_r = mw * 64 + (lane & 15);
  const int a_c = (lane & 16) ? 8 : 0;
  const int b_r = nw * 32 + (lane & 7) + ((lane & 16) ? 8 : 0);
  const int b_c = (lane & 8) ? 8 : 0;

  issue(0, 0);
  CPA_WAIT(0);
  __syncthreads();

  int buf = 0;
  for (int kt = 0; kt < 32; kt++) {
    if (kt < 31) issue(kt + 1, buf ^ 1);

    const unsigned bbase = sb32 + buf * (BUFE * 2);
#pragma unroll
    for (int ks = 0; ks < 2; ks++) {
      const int k0 = ks << 4;
      unsigned ahi[4][4], alo[4][4], bhi[2][4], blo[2][4];
      unsigned aaddr = bbase + (unsigned)((a_r * SA + k0 + a_c) << 1);
#pragma unroll
      for (int mf = 0; mf < 4; mf++) {
        LDSM4(ahi[mf], aaddr + mf * (16 * SA * 2));
        LDSM4(alo[mf], aaddr + mf * (16 * SA * 2) + PLANE * 2);
      }
      unsigned baddr =
          bbase + (unsigned)(((2 * PLANE) + b_r * SA + k0 + b_c) << 1);
#pragma unroll
      for (int nf2 = 0; nf2 < 2; nf2++) {
        LDSM4(bhi[nf2], baddr + nf2 * (16 * SA * 2));
        LDSM4(blo[nf2], baddr + nf2 * (16 * SA * 2) + PLANE * 2);
      }
#pragma unroll
      for (int mf = 0; mf < 4; mf++)
#pragma unroll
        for (int nf = 0; nf < 4; nf++) {
          const int g = nf >> 1, hh = (nf & 1) << 1;
          MMA16816(acc[mf][nf], ahi[mf], bhi[g][hh], bhi[g][hh + 1]);
          MMA16816(acc[mf][nf], ahi[mf], blo[g][hh], blo[g][hh + 1]);
          MMA16816(acc[mf][nf], alo[mf], bhi[g][hh], bhi[g][hh + 1]);
        }
    }

    if (kt < 31) {
      CPA_WAIT(0);
      __syncthreads();
      buf ^= 1;
    }
  }

  const int erow = m0 + mw * 64 + (lane >> 2);
  const int ecol = n0 + nw * 32 + ((lane & 3) << 1);
#pragma unroll
  for (int mf = 0; mf < 4; mf++)
#pragma unroll
    for (int nf = 0; nf < 4; nf++) {
      if (EPI == 0) {
        float* yp = Y + (size_t)(erow + mf * 16) * 1024 + ecol + nf * 8;
        float2 lo2 = {acc[mf][nf][0], acc[mf][nf][1]};
        float2 hi2 = {acc[mf][nf][2], acc[mf][nf][3]};
        *(float2*)yp = lo2;
        *(float2*)(yp + 8 * 1024) = hi2;
      } else {
#pragma unroll
        for (int p = 0; p < 2; p++) {
          float a = acc[mf][nf][2 * p], b2 = acc[mf][nf][2 * p + 1];
          __nv_bfloat16 ha = __float2bfloat16(a), hb = __float2bfloat16(b2);
          size_t addr = (size_t)(erow + mf * 16 + p * 8) * 1024 + ecol + nf * 8;
          *(unsigned*)&Yh[addr] = pack_bf16(a, b2);
          *(unsigned*)&Yl[addr] = pack_bf16(a - __bfloat162float(ha),
                                            b2 - __bfloat162float(hb));
        }
      }
    }
}

// ---------------------------------------------------------------------------
// RoPE + split: fp32 q/k -> rotated bf16 hi/lo planes (pairwise variant).
// ---------------------------------------------------------------------------
__global__ void rope_split_kernel(
    const float* __restrict__ Qf, const float* __restrict__ Kf,
    __nv_bfloat16* __restrict__ qh, __nv_bfloat16* __restrict__ ql,
    __nv_bfloat16* __restrict__ kh, __nv_bfloat16* __restrict__ kl) {
  const int total = BB * SS * HH * (DK / 2);
  int p = blockIdx.x * blockDim.x + threadIdx.x;
  if (p >= total) return;
  const int i = p & 31;
  const int s = (p >> 9) & (SS - 1);
  const int m0 = (2 * i) & 31;
  const int m1 = (2 * i + 1) & 31;
  const float L = 0.41524101186091903f;  // log2(10000)/32
  float a0 = (float)s * exp2f(-(float)m0 * L);
  float a1 = (float)s * exp2f(-(float)m1 * L);
  const double INV2PI = 0.15915494309189535;
  const double TWOPI = 6.283185307179586;
  double r0 = (double)a0 - floor((double)a0 * INV2PI) * TWOPI;
  double r1 = (double)a1 - floor((double)a1 * INV2PI) * TWOPI;
  float c0 = cosf((float)r0), s0 = sinf((float)r0);
  float c1 = cosf((float)r1), s1 = sinf((float)r1);

  float2 xq = ((const float2*)Qf)[p];
  float2 xk = ((const float2*)Kf)[p];
  float oq0 = xq.x * c0 - xq.y * s0;
  float oq1 = xq.x * s1 + xq.y * c1;
  float ok0 = xk.x * c0 - xk.y * s0;
  float ok1 = xk.x * s1 + xk.y * c1;

  __nv_bfloat16 qh0 = __float2bfloat16(oq0), qh1 = __float2bfloat16(oq1);
  __nv_bfloat16 kh0 = __float2bfloat16(ok0), kh1 = __float2bfloat16(ok1);
  *(__nv_bfloat162*)(qh + 2 * p) = __halves2bfloat162(qh0, qh1);
  *(__nv_bfloat162*)(ql + 2 * p) = __halves2bfloat162(
      __float2bfloat16(oq0 - __bfloat162float(qh0)),
      __float2bfloat16(oq1 - __bfloat162float(qh1)));
  *(__nv_bfloat162*)(kh + 2 * p) = __halves2bfloat162(kh0, kh1);
  *(__nv_bfloat162*)(kl + 2 * p) = __halves2bfloat162(
      __float2bfloat16(ok0 - __bfloat162float(kh0)),
      __float2bfloat16(ok1 - __bfloat162float(kh1)));
}

// ---------------------------------------------------------------------------
// MMA flash attention: causal, bf16x3, fp32 softmax/acc, cp.async double
// buffered K/V. CTA = 64 q-rows of one (b,h), 128 threads. Output written
// directly as bf16 hi/lo planes. grid (B*H=32, 32), qt reversed.
// ---------------------------------------------------------------------------
#define AST 72
#define PL2 (64 * AST * 2)          // bytes per plane
#define STAGE_B (4 * PL2)           // bytes per stage (4 planes)
#define ATTN_SMEM (2 * STAGE_B)     // 73728 B

__global__ __launch_bounds__(128) void attn_mma(
    const __nv_bfloat16* __restrict__ Qh, const __nv_bfloat16* __restrict__ Ql,
    const __nv_bfloat16* __restrict__ Kh, const __nv_bfloat16* __restrict__ Kl,
    const __nv_bfloat16* __restrict__ Vh, const __nv_bfloat16* __restrict__ Vl,
    __nv_bfloat16* __restrict__ XoH, __nv_bfloat16* __restrict__ XoL) {
  extern __shared__ __nv_bfloat16 as_[];
  const unsigned s_base = (unsigned)__cvta_generic_to_shared(as_);

  const int t = threadIdx.x;
  const int lane = t & 31;
  const int wi = t >> 5;
  const int b = blockIdx.x >> 4;
  const int h = blockIdx.x & 15;
  const int qt = (int)gridDim.y - 1 - (int)blockIdx.y;
  const size_t base = (size_t)b * SS * DD + h * DK;

  // ---- stage Q tile through buffer-0 planes, pull A-frags to registers ----
  {
    __nv_bfloat16* q0h = as_;
    __nv_bfloat16* q0l = as_ + 64 * AST;
    for (int idx = t; idx < 512; idx += 128) {
      int r = idx >> 3, c = (idx & 7) << 3;
      size_t g = base + (size_t)(qt * 64 + r) * DD + c;
      *(uint4*)&q0h[r * AST + c] = *(const uint4*)&Qh[g];
      *(uint4*)&q0l[r * AST + c] = *(const uint4*)&Ql[g];
    }
  }
  __syncthreads();
  const int a_r = wi * 16 + (lane & 15);
  const int a_c = (lane & 16) ? 8 : 0;
  unsigned qfh[4][4], qfl[4][4];
#pragma unroll
  for (int kc = 0; kc < 4; kc++) {
    unsigned ad = s_base + (unsigned)((a_r * AST + kc * 16 + a_c) << 1);
    LDSM4(qfh[kc], ad);
    LDSM4(qfl[kc], ad + PL2);
  }
  __syncthreads();

  auto issue_tile = [&](int j, int bufi) {
    const unsigned kb = s_base + bufi * STAGE_B;
    for (int idx = t; idx < 512; idx += 128) {
      int r = idx >> 3, c = (idx & 7) << 3;
      size_t g = base + (size_t)(j * 64 + r) * DD + c;
      unsigned off = (unsigned)((r * AST + c) << 1);
      CPA16(kb + off, Kh + g);
      CPA16(kb + PL2 + off, Kl + g);
      CPA16(kb + 2 * PL2 + off, Vh + g);
      CPA16(kb + 3 * PL2 + off, Vl + g);
    }
    CPA_COMMIT();
  };

  const int b_r = (lane & 7) + ((lane & 16) ? 8 : 0);
  const int b_c = (lane & 8) ? 8 : 0;
  const int v_r = lane & 15;
  const int v_c = ((lane >> 4) & 1) << 3;

  float o[8][4] = {};
  float mrow[2] = {-INFINITY, -INFINITY};
  float lrow[2] = {0.f, 0.f};
  const int grow0 = qt * 64 + wi * 16 + (lane >> 2);
  const int gcol0 = (lane & 3) << 1;

  issue_tile(0, 0);
  int buf = 0;
  for (int j = 0; j <= qt; j++) {
    if (j < qt) {
      issue_tile(j + 1, buf ^ 1);
      CPA_WAIT(1);
    } else {
      CPA_WAIT(0);
    }
    __syncthreads();
    const unsigned kb = s_base + buf * STAGE_B;
    const unsigned vb = kb + 2 * PL2;

    // ---- S = Q K^T  (bf16x3) ----
    float sc[8][4] = {};
#pragma unroll
    for (int kc = 0; kc < 4; kc++) {
      unsigned bh[4][4], bl[4][4];
#pragma unroll
      for (int g2 = 0; g2 < 4; g2++) {
        unsigned ad =
            kb + (unsigned)(((g2 * 16 + b_r) * AST + kc * 16 + b_c) << 1);
        LDSM4(bh[g2], ad);
        LDSM4(bl[g2], ad + PL2);
      }
#pragma unroll
      for (int nf = 0; nf < 8; nf++) {
        const int g2 = nf >> 1, hh = (nf & 1) << 1;
        MMA16816(sc[nf], qfh[kc], bh[g2][hh], bh[g2][hh + 1]);
        MMA16816(sc[nf], qfh[kc], bl[g2][hh], bl[g2][hh + 1]);
        MMA16816(sc[nf], qfl[kc], bh[g2][hh], bh[g2][hh + 1]);
      }
    }

    // ---- scale + causal mask ----
    const float SC = 0.125f;  // 1/sqrt(64)
    if (j == qt) {
#pragma unroll
      for (int nf = 0; nf < 8; nf++)
#pragma unroll
        for (int e = 0; e < 4; e++) {
          int col = j * 64 + nf * 8 + gcol0 + (e & 1);
          int row = grow0 + ((e >> 1) << 3);
          sc[nf][e] = (col > row) ? -INFINITY : sc[nf][e] * SC;
        }
    } else {
#pragma unroll
      for (int nf = 0; nf < 8; nf++)
#pragma unroll
        for (int e = 0; e < 4; e++) sc[nf][e] *= SC;
    }

    // ---- online softmax ----
#pragma unroll
    for (int i = 0; i < 2; i++) {
      float tm = -INFINITY;
#pragma unroll
      for (int nf = 0; nf < 8; nf++)
        tm = fmaxf(tm, fmaxf(sc[nf][2 * i], sc[nf][2 * i + 1]));
      tm = fmaxf(tm, __shfl_xor_sync(0xffffffffu, tm, 1));
      tm = fmaxf(tm, __shfl_xor_sync(0xffffffffu, tm, 2));
      float mn = fmaxf(mrow[i], tm);
      float corr = __expf(mrow[i] - mn);
      float ps = 0.f;
#pragma unroll
      for (int nf = 0; nf < 8; nf++) {
        float p0 = __expf(sc[nf][2 * i] - mn);
        float p1 = __expf(sc[nf][2 * i + 1] - mn);
        sc[nf][2 * i] = p0;
        sc[nf][2 * i + 1] = p1;
        ps += p0 + p1;
      }
      ps += __shfl_xor_sync(0xffffffffu, ps, 1);
      ps += __shfl_xor_sync(0xffffffffu, ps, 2);
      lrow[i] = lrow[i] * corr + ps;
      mrow[i] = mn;
#pragma unroll
      for (int nf = 0; nf < 8; nf++) {
        o[nf][2 * i] *= corr;
        o[nf][2 * i + 1] *= corr;
      }
    }

    // ---- O += P V ----
#pragma unroll
    for (int kc = 0; kc < 4; kc++) {
      unsigned pa[4], pl[4];
#pragma unroll
      for (int rr = 0; rr < 2; rr++) {
        float f0 = sc[2 * kc + rr][0], f1 = sc[2 * kc + rr][1];
        float f2 = sc[2 * kc + rr][2], f3 = sc[2 * kc + rr][3];
        __nv_bfloat16 h0 = __float2bfloat16(f0), h1 = __float2bfloat16(f1);
        __nv_bfloat16 h2 = __float2bfloat16(f2), h3 = __float2bfloat16(f3);
        pa[2 * rr] = pack_bf16(f0, f1);
        pa[2 * rr + 1] = pack_bf16(f2, f3);
        pl[2 * rr] = pack_bf16(f0 - __bfloat162float(h0),
                               f1 - __bfloat162float(h1));
        pl[2 * rr + 1] = pack_bf16(f2 - __bfloat162float(h2),
                                   f3 - __bfloat162float(h3));
      }
      unsigned wvh[4][4], wvl[4][4];
#pragma unroll
      for (int g2 = 0; g2 < 4; g2++) {
        unsigned ad =
            vb + (unsigned)(((kc * 16 + v_r) * AST + g2 * 16 + v_c) << 1);
        LDSM4T(wvh[g2], ad);
        LDSM4T(wvl[g2], ad + PL2);
      }
#pragma unroll
      for (int nf = 0; nf < 8; nf++) {
        const int g2 = nf >> 1, hh = (nf & 1) << 1;
        MMA16816(o[nf], pa, wvh[g2][hh], wvh[g2][hh + 1]);
        MMA16816(o[nf], pa, wvl[g2][hh], wvl[g2][hh + 1]);
        MMA16816(o[nf], pl, wvh[g2][hh], wvh[g2][hh + 1]);
      }
    }
    __syncthreads();  // all reads of buf done before next issue overwrites
    buf ^= 1;
  }

  // ---- finalize: write hi/lo planes directly ----
#pragma unroll
  for (int i = 0; i < 2; i++) {
    float inv = 1.f / lrow[i];
    int row = grow0 + i * 8;
#pragma unroll
    for (int nf = 0; nf < 8; nf++) {
      float a = o[nf][2 * i] * inv, b2 = o[nf][2 * i + 1] * inv;
      __nv_bfloat16 ha = __float2bfloat16(a), hb = __float2bfloat16(b2);
      size_t addr = (size_t)(b * SS + row) * DD + h * DK + nf * 8 + gcol0;
      *(unsigned*)&XoH[addr] = pack_bf16(a, b2);
      *(unsigned*)&XoL[addr] =
          pack_bf16(a - __bfloat162float(ha), b2 - __bfloat162float(hb));
    }
  }
}

// ---------------------------------------------------------------------------
// kernel_launch
// Inputs: 0=q, 1=k, 2=v, 3=mask (ignored: tril causal), 4=wq, 5=wk, 6=wv, 7=wo
// ---------------------------------------------------------------------------
extern "C" void kernel_launch(void* const* d_in, const int* in_sizes, int n_in,
                              void* d_out, int out_size) {
  (void)in_sizes; (void)n_in; (void)out_size;
  const float* q = (const float*)d_in[0];
  const float* k = (const float*)d_in[1];
  const float* v = (const float*)d_in[2];
  const float* wq = (const float*)d_in[4];
  const float* wk = (const float*)d_in[5];
  const float* wv = (const float*)d_in[6];
  const float* wo = (const float*)d_in[7];
  float* out = (float*)d_out;

  float *pq, *pk;
  cudaGetSymbolAddress((void**)&pq, g_q);
  cudaGetSymbolAddress((void**)&pk, g_k);
  __nv_bfloat16 *qh, *ql, *kh, *kl, *vh, *vl, *xh, *xl, *yh, *yl;
  cudaGetSymbolAddress((void**)&qh, g_qh); cudaGetSymbolAddress((void**)&ql, g_ql);
  cudaGetSymbolAddress((void**)&kh, g_kh); cudaGetSymbolAddress((void**)&kl, g_kl);
  cudaGetSymbolAddress((void**)&vh, g_vh); cudaGetSymbolAddress((void**)&vl, g_vl);
  cudaGetSymbolAddress((void**)&xh, g_xh); cudaGetSymbolAddress((void**)&xl, g_xl);
  cudaGetSymbolAddress((void**)&yh, g_yh); cudaGetSymbolAddress((void**)&yl, g_yl);
  __nv_bfloat16 *wqh, *wql, *wkh, *wkl, *wvh, *wvl, *woh, *wol;
  cudaGetSymbolAddress((void**)&wqh, g_wqh); cudaGetSymbolAddress((void**)&wql, g_wql);
  cudaGetSymbolAddress((void**)&wkh, g_wkh); cudaGetSymbolAddress((void**)&wkl, g_wkl);
  cudaGetSymbolAddress((void**)&wvh, g_wvh); cudaGetSymbolAddress((void**)&wvl, g_wvl);
  cudaGetSymbolAddress((void**)&woh, g_woh); cudaGetSymbolAddress((void**)&wol, g_wol);

  cudaFuncSetAttribute(gemm_cpa<0>, cudaFuncAttributeMaxDynamicSharedMemorySize,
                       GEMM_SMEM);
  cudaFuncSetAttribute(gemm_cpa<1>, cudaFuncAttributeMaxDynamicSharedMemorySize,
                       GEMM_SMEM);
  cudaFuncSetAttribute(attn_mma, cudaFuncAttributeMaxDynamicSharedMemorySize,
                       ATTN_SMEM);

  // split inputs + weights
  split_kernel<<<NEL / 1024, 256>>>(q, qh, ql, NEL);
  split_kernel<<<NEL / 1024, 256>>>(k, kh, kl, NEL);
  split_kernel<<<NEL / 1024, 256>>>(v, vh, vl, NEL);
  split_kernel<<<WEL / 1024, 256>>>(wq, wqh, wql, WEL);
  split_kernel<<<WEL / 1024, 256>>>(wk, wkh, wkl, WEL);
  split_kernel<<<WEL / 1024, 256>>>(wv, wvh, wvl, WEL);
  split_kernel<<<WEL / 1024, 256>>>(wo, woh, wol, WEL);

  // projections: q,k -> fp32 (rope needs fp32); v -> bf16 planes directly
  dim3 ggrid(8, 32);
  gemm_cpa<0><<<ggrid, 256, GEMM_SMEM>>>(qh, ql, wqh, wql, pq, nullptr, nullptr);
  gemm_cpa<0><<<ggrid, 256, GEMM_SMEM>>>(kh, kl, wkh, wkl, pk, nullptr, nullptr);
  gemm_cpa<1><<<ggrid, 256, GEMM_SMEM>>>(vh, vl, wvh, wvl, nullptr, xh, xl);

  // rope + re-split (reuse input q/k planes)
  const int pairs = BB * SS * HH * (DK / 2);
  rope_split_kernel<<<pairs / 256, 256>>>(pq, pk, qh, ql, kh, kl);

  // attention (V planes = xh/xl), writes bf16 planes yh/yl directly
  attn_mma<<<dim3(BB * HH, SS / 64), 128, ATTN_SMEM>>>(qh, ql, kh, kl, xh, xl,
                                                       yh, yl);

  // output projection
  gemm_cpa<0><<<ggrid, 256, GEMM_SMEM>>>(yh, yl, woh, wol, out, nullptr,
                                         nullptr);
}

// round 10
// speedup vs baseline: 2.4372x; 1.0054x over previous
#include <cuda_runtime.h>
#include <cuda_bf16.h>
#include <math.h>

// Problem constants
#define BB 2
#define SS 2048
#define DD 1024
#define HH 16
#define DK 64
#define NROWS (BB * SS)   // 4096
#define NEL (NROWS * DD)  // 4M
#define WEL (DD * DD)     // 1M

// ---------------------------------------------------------------------------
// Scratch (device globals -- no allocation allowed)
// ---------------------------------------------------------------------------
// input planes
__device__ __nv_bfloat16 g_qh[NEL], g_ql[NEL];
__device__ __nv_bfloat16 g_kh[NEL], g_kl[NEL];
__device__ __nv_bfloat16 g_vh[NEL], g_vl[NEL];
// projection outputs (rope'd q/k, projected v)
__device__ __nv_bfloat16 g_oqh[NEL], g_oql[NEL];
__device__ __nv_bfloat16 g_okh[NEL], g_okl[NEL];
__device__ __nv_bfloat16 g_xh[NEL], g_xl[NEL];
// attention output planes
__device__ __nv_bfloat16 g_yh[NEL], g_yl[NEL];
// weight planes
__device__ __nv_bfloat16 g_wqh[WEL], g_wql[WEL];
__device__ __nv_bfloat16 g_wkh[WEL], g_wkl[WEL];
__device__ __nv_bfloat16 g_wvh[WEL], g_wvl[WEL];
__device__ __nv_bfloat16 g_woh[WEL], g_wol[WEL];
// rope tables [SS][DK]
__device__ float g_ct[SS * DK];
__device__ float g_st[SS * DK];

// ---------------------------------------------------------------------------
// Primitives
// ---------------------------------------------------------------------------
#define LDSM4(R, addr)                                                   \
  asm volatile(                                                          \
      "ldmatrix.sync.aligned.m8n8.x4.shared.b16 {%0,%1,%2,%3},[%4];"     \
      : "=r"((R)[0]), "=r"((R)[1]), "=r"((R)[2]), "=r"((R)[3])           \
      : "r"(addr))

#define LDSM4T(R, addr)                                                  \
  asm volatile(                                                          \
      "ldmatrix.sync.aligned.m8n8.x4.trans.shared.b16 {%0,%1,%2,%3},[%4];" \
      : "=r"((R)[0]), "=r"((R)[1]), "=r"((R)[2]), "=r"((R)[3])           \
      : "r"(addr))

#define MMA16816(C, A, B0, B1)                                           \
  asm volatile(                                                          \
      "mma.sync.aligned.m16n8k16.row.col.f32.bf16.bf16.f32 "             \
      "{%0,%1,%2,%3},{%4,%5,%6,%7},{%8,%9},{%0,%1,%2,%3};"               \
      : "+f"((C)[0]), "+f"((C)[1]), "+f"((C)[2]), "+f"((C)[3])           \
      : "r"((A)[0]), "r"((A)[1]), "r"((A)[2]), "r"((A)[3]), "r"(B0),     \
        "r"(B1))

#define CPA16(dst, src)                                                  \
  asm volatile("cp.async.cg.shared.global [%0], [%1], 16;" ::"r"(dst),   \
               "l"(src))
#define CPA_COMMIT() asm volatile("cp.async.commit_group;" ::)
#define CPA_WAIT(n) asm volatile("cp.async.wait_group %0;" ::"n"(n))

__device__ __forceinline__ unsigned pack_bf16(float a, float b) {
  __nv_bfloat162 t = __halves2bfloat162(__float2bfloat16(a), __float2bfloat16(b));
  return *(unsigned*)&t;
}

// ---------------------------------------------------------------------------
// rope table: ct/st[s][j] = cos/sin(s * 10000^{-(j mod 32)/32}),
// fp32 angle + double range reduction (matches reference numerics).
// ---------------------------------------------------------------------------
__global__ void rope_table_kernel(float* __restrict__ ct,
                                  float* __restrict__ st) {
  int idx = blockIdx.x * blockDim.x + threadIdx.x;  // SS*DK = 131072
  int s = idx >> 6;
  int m = idx & 31;  // j mod 32
  const float L = 0.41524101186091903f;  // log2(10000)/32
  float a = (float)s * exp2f(-(float)m * L);
  const double INV2PI = 0.15915494309189535;
  const double TWOPI = 6.283185307179586;
  double r = (double)a - floor((double)a * INV2PI) * TWOPI;
  ct[idx] = cosf((float)r);
  st[idx] = sinf((float)r);
}

// ---------------------------------------------------------------------------
// batched splits: fp32 -> (hi, lo) bf16 planes. gridDim.z selects tensor.
// ---------------------------------------------------------------------------
__global__ void split3_kernel(const float* __restrict__ x0,
                              const float* __restrict__ x1,
                              const float* __restrict__ x2,
                              __nv_bfloat16* h0, __nv_bfloat16* l0,
                              __nv_bfloat16* h1, __nv_bfloat16* l1,
                              __nv_bfloat16* h2, __nv_bfloat16* l2) {
  const float* x;
  __nv_bfloat16 *hi, *lo;
  if (blockIdx.z == 0) { x = x0; hi = h0; lo = l0; }
  else if (blockIdx.z == 1) { x = x1; hi = h1; lo = l1; }
  else { x = x2; hi = h2; lo = l2; }
  int i = (blockIdx.x * blockDim.x + threadIdx.x) << 2;
  float4 v = *(const float4*)(x + i);
  float f[4] = {v.x, v.y, v.z, v.w};
  __nv_bfloat16 h[4], l[4];
#pragma unroll
  for (int j = 0; j < 4; j++) {
    h[j] = __float2bfloat16(f[j]);
    l[j] = __float2bfloat16(f[j] - __bfloat162float(h[j]));
  }
  *(__nv_bfloat162*)(hi + i) = __halves2bfloat162(h[0], h[1]);
  *(__nv_bfloat162*)(hi + i + 2) = __halves2bfloat162(h[2], h[3]);
  *(__nv_bfloat162*)(lo + i) = __halves2bfloat162(l[0], l[1]);
  *(__nv_bfloat162*)(lo + i + 2) = __halves2bfloat162(l[2], l[3]);
}

__global__ void split4_kernel(const float* __restrict__ x0,
                              const float* __restrict__ x1,
                              const float* __restrict__ x2,
                              const float* __restrict__ x3,
                              __nv_bfloat16* h0, __nv_bfloat16* l0,
                              __nv_bfloat16* h1, __nv_bfloat16* l1,
                              __nv_bfloat16* h2, __nv_bfloat16* l2,
                              __nv_bfloat16* h3, __nv_bfloat16* l3) {
  const float* x;
  __nv_bfloat16 *hi, *lo;
  if (blockIdx.z == 0) { x = x0; hi = h0; lo = l0; }
  else if (blockIdx.z == 1) { x = x1; hi = h1; lo = l1; }
  else if (blockIdx.z == 2) { x = x2; hi = h2; lo = l2; }
  else { x = x3; hi = h3; lo = l3; }
  int i = (blockIdx.x * blockDim.x + threadIdx.x) << 2;
  float4 v = *(const float4*)(x + i);
  float f[4] = {v.x, v.y, v.z, v.w};
  __nv_bfloat16 h[4], l[4];
#pragma unroll
  for (int j = 0; j < 4; j++) {
    h[j] = __float2bfloat16(f[j]);
    l[j] = __float2bfloat16(f[j] - __bfloat162float(h[j]));
  }
  *(__nv_bfloat162*)(hi + i) = __halves2bfloat162(h[0], h[1]);
  *(__nv_bfloat162*)(hi + i + 2) = __halves2bfloat162(h[2], h[3]);
  *(__nv_bfloat162*)(lo + i) = __halves2bfloat162(l[0], l[1]);
  *(__nv_bfloat162*)(lo + i + 2) = __halves2bfloat162(l[2], l[3]);
}

// ---------------------------------------------------------------------------
// GEMM core (cp.async 2-stage, bf16x3). Shared by both GEMM kernels.
// CTA 128x128, K_STEP 32, 8 warps (2m x 4n), warp 64x32.
// ---------------------------------------------------------------------------
#define SA 40
#define PLANE (128 * SA)            // 5120 bf16 per plane
#define BUFE (4 * PLANE)            // AHI, ALO, BHI, BLO
#define GEMM_SMEM (2 * BUFE * 2)    // 81920 bytes

struct GemmCore {
  unsigned sb32;
  const __nv_bfloat16 *xh, *xl, *wh, *wl;
  unsigned sdst;
  int a_r, a_c, b_r, b_c;

  __device__ __forceinline__ void init(const __nv_bfloat16* Xh,
                                       const __nv_bfloat16* Xl,
                                       const __nv_bfloat16* Wh,
                                       const __nv_bfloat16* Wl, int m0, int n0,
                                       unsigned smem_base, int t) {
    sb32 = smem_base;
    const int lane = t & 31;
    const int w = t >> 5;
    const int mw = w & 1;
    const int nw = w >> 1;
    const int grow = t >> 1;
    const int gkh = (t & 1) << 4;
    xh = Xh + (size_t)(m0 + grow) * 1024 + gkh;
    xl = Xl + (size_t)(m0 + grow) * 1024 + gkh;
    wh = Wh + (size_t)(n0 + grow) * 1024 + gkh;
    wl = Wl + (size_t)(n0 + grow) * 1024 + gkh;
    sdst = sb32 + (unsigned)((grow * SA + gkh) << 1);
    a_r = mw * 64 + (lane & 15);
    a_c = (lane & 16) ? 8 : 0;
    b_r = nw * 32 + (lane & 7) + ((lane & 16) ? 8 : 0);
    b_c = (lane & 8) ? 8 : 0;
  }

  __device__ __forceinline__ void issue(int kt, int bufi) {
    const unsigned d = sdst + (unsigned)(bufi * (BUFE * 2));
    const int o_ = kt * 32;
    CPA16(d, xh + o_);
    CPA16(d + 16, xh + o_ + 8);
    CPA16(d + PLANE * 2, xl + o_);
    CPA16(d + PLANE * 2 + 16, xl + o_ + 8);
    CPA16(d + 2 * PLANE * 2, wh + o_);
    CPA16(d + 2 * PLANE * 2 + 16, wh + o_ + 8);
    CPA16(d + 3 * PLANE * 2, wl + o_);
    CPA16(d + 3 * PLANE * 2 + 16, wl + o_ + 8);
    CPA_COMMIT();
  }

  __device__ __forceinline__ void run(float acc[4][4][4]) {
    issue(0, 0);
    CPA_WAIT(0);
    __syncthreads();
    int buf = 0;
    for (int kt = 0; kt < 32; kt++) {
      if (kt < 31) issue(kt + 1, buf ^ 1);
      const unsigned bbase = sb32 + buf * (BUFE * 2);
#pragma unroll
      for (int ks = 0; ks < 2; ks++) {
        const int k0 = ks << 4;
        unsigned ahi[4][4], alo[4][4], bhi[2][4], blo[2][4];
        unsigned aaddr = bbase + (unsigned)((a_r * SA + k0 + a_c) << 1);
#pragma unroll
        for (int mf = 0; mf < 4; mf++) {
          LDSM4(ahi[mf], aaddr + mf * (16 * SA * 2));
          LDSM4(alo[mf], aaddr + mf * (16 * SA * 2) + PLANE * 2);
        }
        unsigned baddr =
            bbase + (unsigned)(((2 * PLANE) + b_r * SA + k0 + b_c) << 1);
#pragma unroll
        for (int nf2 = 0; nf2 < 2; nf2++) {
          LDSM4(bhi[nf2], baddr + nf2 * (16 * SA * 2));
          LDSM4(blo[nf2], baddr + nf2 * (16 * SA * 2) + PLANE * 2);
        }
#pragma unroll
        for (int mf = 0; mf < 4; mf++)
#pragma unroll
          for (int nf = 0; nf < 4; nf++) {
            const int g = nf >> 1, hh = (nf & 1) << 1;
            MMA16816(acc[mf][nf], ahi[mf], bhi[g][hh], bhi[g][hh + 1]);
            MMA16816(acc[mf][nf], ahi[mf], blo[g][hh], blo[g][hh + 1]);
            MMA16816(acc[mf][nf], alo[mf], bhi[g][hh], bhi[g][hh + 1]);
          }
      }
      if (kt < 31) {
        CPA_WAIT(0);
        __syncthreads();
        buf ^= 1;
      }
    }
  }
};

// ---------------------------------------------------------------------------
// Merged q/k/v projection GEMM. grid (8, 32, 3); z: 0=q(rope),1=k(rope),2=v.
// Outputs bf16 hi/lo planes directly; q/k get RoPE applied to the fp32
// accumulators via the precomputed tables (thread-local: c-frag owns the
// (2i, 2i+1) column pairs).
// ---------------------------------------------------------------------------
__global__ __launch_bounds__(256) void gemm_qkv(
    const __nv_bfloat16* __restrict__ Qh, const __nv_bfloat16* __restrict__ Ql,
    const __nv_bfloat16* __restrict__ Kh, const __nv_bfloat16* __restrict__ Kl,
    const __nv_bfloat16* __restrict__ Vh, const __nv_bfloat16* __restrict__ Vl,
    const __nv_bfloat16* __restrict__ Wqh, const __nv_bfloat16* __restrict__ Wql,
    const __nv_bfloat16* __restrict__ Wkh, const __nv_bfloat16* __restrict__ Wkl,
    const __nv_bfloat16* __restrict__ Wvh, const __nv_bfloat16* __restrict__ Wvl,
    __nv_bfloat16* __restrict__ Oqh, __nv_bfloat16* __restrict__ Oql,
    __nv_bfloat16* __restrict__ Okh, __nv_bfloat16* __restrict__ Okl,
    __nv_bfloat16* __restrict__ Ovh, __nv_bfloat16* __restrict__ Ovl,
    const float* __restrict__ CT, const float* __restrict__ ST) {
  extern __shared__ __nv_bfloat16 sb[];
  const int z = blockIdx.z;
  const __nv_bfloat16 *Xh, *Xl, *Wh, *Wl;
  __nv_bfloat16 *Yh, *Yl;
  if (z == 0) { Xh = Qh; Xl = Ql; Wh = Wqh; Wl = Wql; Yh = Oqh; Yl = Oql; }
  else if (z == 1) { Xh = Kh; Xl = Kl; Wh = Wkh; Wl = Wkl; Yh = Okh; Yl = Okl; }
  else { Xh = Vh; Xl = Vl; Wh = Wvh; Wl = Wvl; Yh = Ovh; Yl = Ovl; }

  const int t = threadIdx.x;
  const int lane = t & 31;
  const int w = t >> 5;
  const int m0 = blockIdx.y * 128;
  const int n0 = blockIdx.x * 128;

  GemmCore core;
  core.init(Xh, Xl, Wh, Wl, m0, n0,
            (unsigned)__cvta_generic_to_shared(sb), t);
  float acc[4][4][4] = {};
  core.run(acc);

  const int erow = m0 + (w & 1) * 64 + (lane >> 2);
  const int ecol = n0 + (w >> 1) * 32 + ((lane & 3) << 1);
  const bool dorope = (z < 2);
#pragma unroll
  for (int mf = 0; mf < 4; mf++)
#pragma unroll
    for (int nf = 0; nf < 4; nf++) {
      const int colbase = ecol + nf * 8;
      const int j = colbase & 63;
#pragma unroll
      for (int p = 0; p < 2; p++) {
        const int row = erow + mf * 16 + p * 8;
        float a0 = acc[mf][nf][2 * p], a1 = acc[mf][nf][2 * p + 1];
        if (dorope) {
          const int s = row & (SS - 1);
          float c0 = CT[s * 64 + j], s0v = ST[s * 64 + j];
          float c1 = CT[s * 64 + j + 1], s1v = ST[s * 64 + j + 1];
          float r0 = a0 * c0 - a1 * s0v;
          float r1 = a0 * s1v + a1 * c1;
          a0 = r0;
          a1 = r1;
        }
        __nv_bfloat16 ha = __float2bfloat16(a0), hb = __float2bfloat16(a1);
        size_t addr = (size_t)row * 1024 + colbase;
        *(unsigned*)&Yh[addr] = pack_bf16(a0, a1);
        *(unsigned*)&Yl[addr] = pack_bf16(a0 - __bfloat162float(ha),
                                          a1 - __bfloat162float(hb));
      }
    }
}

// ---------------------------------------------------------------------------
// Final projection GEMM: planes -> fp32 out.
// ---------------------------------------------------------------------------
__global__ __launch_bounds__(256) void gemm_out(
    const __nv_bfloat16* __restrict__ Xh, const __nv_bfloat16* __restrict__ Xl,
    const __nv_bfloat16* __restrict__ Wh, const __nv_bfloat16* __restrict__ Wl,
    float* __restrict__ Y) {
  extern __shared__ __nv_bfloat16 sb[];
  const int t = threadIdx.x;
  const int lane = t & 31;
  const int w = t >> 5;
  const int m0 = blockIdx.y * 128;
  const int n0 = blockIdx.x * 128;

  GemmCore core;
  core.init(Xh, Xl, Wh, Wl, m0, n0,
            (unsigned)__cvta_generic_to_shared(sb), t);
  float acc[4][4][4] = {};
  core.run(acc);

  const int erow = m0 + (w & 1) * 64 + (lane >> 2);
  const int ecol = n0 + (w >> 1) * 32 + ((lane & 3) << 1);
#pragma unroll
  for (int mf = 0; mf < 4; mf++)
#pragma unroll
    for (int nf = 0; nf < 4; nf++) {
      float* yp = Y + (size_t)(erow + mf * 16) * 1024 + ecol + nf * 8;
      float2 lo2 = {acc[mf][nf][0], acc[mf][nf][1]};
      float2 hi2 = {acc[mf][nf][2], acc[mf][nf][3]};
      *(float2*)yp = lo2;
      *(float2*)(yp + 8 * 1024) = hi2;
    }
}

// ---------------------------------------------------------------------------
// MMA flash attention: causal, bf16x3, fp32 softmax/acc, cp.async double
// buffered K/V. CTA = 64 q-rows of one (b,h), 128 threads. Output written
// directly as bf16 hi/lo planes. grid (B*H=32, 32), qt reversed.
// ---------------------------------------------------------------------------
#define AST 72
#define PL2 (64 * AST * 2)          // bytes per plane
#define STAGE_B (4 * PL2)           // bytes per stage (4 planes)
#define ATTN_SMEM (2 * STAGE_B)     // 73728 B

__global__ __launch_bounds__(128) void attn_mma(
    const __nv_bfloat16* __restrict__ Qh, const __nv_bfloat16* __restrict__ Ql,
    const __nv_bfloat16* __restrict__ Kh, const __nv_bfloat16* __restrict__ Kl,
    const __nv_bfloat16* __restrict__ Vh, const __nv_bfloat16* __restrict__ Vl,
    __nv_bfloat16* __restrict__ XoH, __nv_bfloat16* __restrict__ XoL) {
  extern __shared__ __nv_bfloat16 as_[];
  const unsigned s_base = (unsigned)__cvta_generic_to_shared(as_);

  const int t = threadIdx.x;
  const int lane = t & 31;
  const int wi = t >> 5;
  const int b = blockIdx.x >> 4;
  const int h = blockIdx.x & 15;
  const int qt = (int)gridDim.y - 1 - (int)blockIdx.y;
  const size_t base = (size_t)b * SS * DD + h * DK;

  // ---- stage Q tile through buffer-0 planes, pull A-frags to registers ----
  {
    __nv_bfloat16* q0h = as_;
    __nv_bfloat16* q0l = as_ + 64 * AST;
    for (int idx = t; idx < 512; idx += 128) {
      int r = idx >> 3, c = (idx & 7) << 3;
      size_t g = base + (size_t)(qt * 64 + r) * DD + c;
      *(uint4*)&q0h[r * AST + c] = *(const uint4*)&Qh[g];
      *(uint4*)&q0l[r * AST + c] = *(const uint4*)&Ql[g];
    }
  }
  __syncthreads();
  const int a_r = wi * 16 + (lane & 15);
  const int a_c = (lane & 16) ? 8 : 0;
  unsigned qfh[4][4], qfl[4][4];
#pragma unroll
  for (int kc = 0; kc < 4; kc++) {
    unsigned ad = s_base + (unsigned)((a_r * AST + kc * 16 + a_c) << 1);
    LDSM4(qfh[kc], ad);
    LDSM4(qfl[kc], ad + PL2);
  }
  __syncthreads();

  auto issue_tile = [&](int j, int bufi) {
    const unsigned kb = s_base + bufi * STAGE_B;
    for (int idx = t; idx < 512; idx += 128) {
      int r = idx >> 3, c = (idx & 7) << 3;
      size_t g = base + (size_t)(j * 64 + r) * DD + c;
      unsigned off = (unsigned)((r * AST + c) << 1);
      CPA16(kb + off, Kh + g);
      CPA16(kb + PL2 + off, Kl + g);
      CPA16(kb + 2 * PL2 + off, Vh + g);
      CPA16(kb + 3 * PL2 + off, Vl + g);
    }
    CPA_COMMIT();
  };

  const int b_r = (lane & 7) + ((lane & 16) ? 8 : 0);
  const int b_c = (lane & 8) ? 8 : 0;
  const int v_r = lane & 15;
  const int v_c = ((lane >> 4) & 1) << 3;

  float o[8][4] = {};
  float mrow[2] = {-INFINITY, -INFINITY};
  float lrow[2] = {0.f, 0.f};
  const int grow0 = qt * 64 + wi * 16 + (lane >> 2);
  const int gcol0 = (lane & 3) << 1;

  issue_tile(0, 0);
  int buf = 0;
  for (int j = 0; j <= qt; j++) {
    if (j < qt) {
      issue_tile(j + 1, buf ^ 1);
      CPA_WAIT(1);
    } else {
      CPA_WAIT(0);
    }
    __syncthreads();
    const unsigned kb = s_base + buf * STAGE_B;
    const unsigned vb = kb + 2 * PL2;

    // ---- S = Q K^T  (bf16x3) ----
    float sc[8][4] = {};
#pragma unroll
    for (int kc = 0; kc < 4; kc++) {
      unsigned bh[4][4], bl[4][4];
#pragma unroll
      for (int g2 = 0; g2 < 4; g2++) {
        unsigned ad =
            kb + (unsigned)(((g2 * 16 + b_r) * AST + kc * 16 + b_c) << 1);
        LDSM4(bh[g2], ad);
        LDSM4(bl[g2], ad + PL2);
      }
#pragma unroll
      for (int nf = 0; nf < 8; nf++) {
        const int g2 = nf >> 1, hh = (nf & 1) << 1;
        MMA16816(sc[nf], qfh[kc], bh[g2][hh], bh[g2][hh + 1]);
        MMA16816(sc[nf], qfh[kc], bl[g2][hh], bl[g2][hh + 1]);
        MMA16816(sc[nf], qfl[kc], bh[g2][hh], bh[g2][hh + 1]);
      }
    }

    // ---- scale + causal mask ----
    const float SC = 0.125f;  // 1/sqrt(64)
    if (j == qt) {
#pragma unroll
      for (int nf = 0; nf < 8; nf++)
#pragma unroll
        for (int e = 0; e < 4; e++) {
          int col = j * 64 + nf * 8 + gcol0 + (e & 1);
          int row = grow0 + ((e >> 1) << 3);
          sc[nf][e] = (col > row) ? -INFINITY : sc[nf][e] * SC;
        }
    } else {
#pragma unroll
      for (int nf = 0; nf < 8; nf++)
#pragma unroll
        for (int e = 0; e < 4; e++) sc[nf][e] *= SC;
    }

    // ---- online softmax ----
#pragma unroll
    for (int i = 0; i < 2; i++) {
      float tm = -INFINITY;
#pragma unroll
      for (int nf = 0; nf < 8; nf++)
        tm = fmaxf(tm, fmaxf(sc[nf][2 * i], sc[nf][2 * i + 1]));
      tm = fmaxf(tm, __shfl_xor_sync(0xffffffffu, tm, 1));
      tm = fmaxf(tm, __shfl_xor_sync(0xffffffffu, tm, 2));
      float mn = fmaxf(mrow[i], tm);
      float corr = __expf(mrow[i] - mn);
      float ps = 0.f;
#pragma unroll
      for (int nf = 0; nf < 8; nf++) {
        float p0 = __expf(sc[nf][2 * i] - mn);
        float p1 = __expf(sc[nf][2 * i + 1] - mn);
        sc[nf][2 * i] = p0;
        sc[nf][2 * i + 1] = p1;
        ps += p0 + p1;
      }
      ps += __shfl_xor_sync(0xffffffffu, ps, 1);
      ps += __shfl_xor_sync(0xffffffffu, ps, 2);
      lrow[i] = lrow[i] * corr + ps;
      mrow[i] = mn;
#pragma unroll
      for (int nf = 0; nf < 8; nf++) {
        o[nf][2 * i] *= corr;
        o[nf][2 * i + 1] *= corr;
      }
    }

    // ---- O += P V ----
#pragma unroll
    for (int kc = 0; kc < 4; kc++) {
      unsigned pa[4], pl[4];
#pragma unroll
      for (int rr = 0; rr < 2; rr++) {
        float f0 = sc[2 * kc + rr][0], f1 = sc[2 * kc + rr][1];
        float f2 = sc[2 * kc + rr][2], f3 = sc[2 * kc + rr][3];
        __nv_bfloat16 h0 = __float2bfloat16(f0), h1 = __float2bfloat16(f1);
        __nv_bfloat16 h2 = __float2bfloat16(f2), h3 = __float2bfloat16(f3);
        pa[2 * rr] = pack_bf16(f0, f1);
        pa[2 * rr + 1] = pack_bf16(f2, f3);
        pl[2 * rr] = pack_bf16(f0 - __bfloat162float(h0),
                               f1 - __bfloat162float(h1));
        pl[2 * rr + 1] = pack_bf16(f2 - __bfloat162float(h2),
                                   f3 - __bfloat162float(h3));
      }
      unsigned wvh[4][4], wvl[4][4];
#pragma unroll
      for (int g2 = 0; g2 < 4; g2++) {
        unsigned ad =
            vb + (unsigned)(((kc * 16 + v_r) * AST + g2 * 16 + v_c) << 1);
        LDSM4T(wvh[g2], ad);
        LDSM4T(wvl[g2], ad + PL2);
      }
#pragma unroll
      for (int nf = 0; nf < 8; nf++) {
        const int g2 = nf >> 1, hh = (nf & 1) << 1;
        MMA16816(o[nf], pa, wvh[g2][hh], wvh[g2][hh + 1]);
        MMA16816(o[nf], pa, wvl[g2][hh], wvl[g2][hh + 1]);
        MMA16816(o[nf], pl, wvh[g2][hh], wvh[g2][hh + 1]);
      }
    }
    __syncthreads();  // all reads of buf done before next issue overwrites
    buf ^= 1;
  }

  // ---- finalize: write hi/lo planes directly ----
#pragma unroll
  for (int i = 0; i < 2; i++) {
    float inv = 1.f / lrow[i];
    int row = grow0 + i * 8;
#pragma unroll
    for (int nf = 0; nf < 8; nf++) {
      float a = o[nf][2 * i] * inv, b2 = o[nf][2 * i + 1] * inv;
      __nv_bfloat16 ha = __float2bfloat16(a), hb = __float2bfloat16(b2);
      size_t addr = (size_t)(b * SS + row) * DD + h * DK + nf * 8 + gcol0;
      *(unsigned*)&XoH[addr] = pack_bf16(a, b2);
      *(unsigned*)&XoL[addr] =
          pack_bf16(a - __bfloat162float(ha), b2 - __bfloat162float(hb));
    }
  }
}

// ---------------------------------------------------------------------------
// kernel_launch
// Inputs: 0=q, 1=k, 2=v, 3=mask (ignored: tril causal), 4=wq, 5=wk, 6=wv, 7=wo
// ---------------------------------------------------------------------------
extern "C" void kernel_launch(void* const* d_in, const int* in_sizes, int n_in,
                              void* d_out, int out_size) {
  (void)in_sizes; (void)n_in; (void)out_size;
  const float* q = (const float*)d_in[0];
  const float* k = (const float*)d_in[1];
  const float* v = (const float*)d_in[2];
  const float* wq = (const float*)d_in[4];
  const float* wk = (const float*)d_in[5];
  const float* wv = (const float*)d_in[6];
  const float* wo = (const float*)d_in[7];
  float* out = (float*)d_out;

  __nv_bfloat16 *qh, *ql, *kh, *kl, *vh, *vl;
  __nv_bfloat16 *oqh, *oql, *okh, *okl, *xh, *xl, *yh, *yl;
  cudaGetSymbolAddress((void**)&qh, g_qh); cudaGetSymbolAddress((void**)&ql, g_ql);
  cudaGetSymbolAddress((void**)&kh, g_kh); cudaGetSymbolAddress((void**)&kl, g_kl);
  cudaGetSymbolAddress((void**)&vh, g_vh); cudaGetSymbolAddress((void**)&vl, g_vl);
  cudaGetSymbolAddress((void**)&oqh, g_oqh); cudaGetSymbolAddress((void**)&oql, g_oql);
  cudaGetSymbolAddress((void**)&okh, g_okh); cudaGetSymbolAddress((void**)&okl, g_okl);
  cudaGetSymbolAddress((void**)&xh, g_xh); cudaGetSymbolAddress((void**)&xl, g_xl);
  cudaGetSymbolAddress((void**)&yh, g_yh); cudaGetSymbolAddress((void**)&yl, g_yl);
  __nv_bfloat16 *wqh, *wql, *wkh, *wkl, *wvh, *wvl, *woh, *wol;
  cudaGetSymbolAddress((void**)&wqh, g_wqh); cudaGetSymbolAddress((void**)&wql, g_wql);
  cudaGetSymbolAddress((void**)&wkh, g_wkh); cudaGetSymbolAddress((void**)&wkl, g_wkl);
  cudaGetSymbolAddress((void**)&wvh, g_wvh); cudaGetSymbolAddress((void**)&wvl, g_wvl);
  cudaGetSymbolAddress((void**)&woh, g_woh); cudaGetSymbolAddress((void**)&wol, g_wol);
  float *ct, *st;
  cudaGetSymbolAddress((void**)&ct, g_ct);
  cudaGetSymbolAddress((void**)&st, g_st);

  cudaFuncSetAttribute(gemm_qkv, cudaFuncAttributeMaxDynamicSharedMemorySize,
                       GEMM_SMEM);
  cudaFuncSetAttribute(gemm_out, cudaFuncAttributeMaxDynamicSharedMemorySize,
                       GEMM_SMEM);
  cudaFuncSetAttribute(attn_mma, cudaFuncAttributeMaxDynamicSharedMemorySize,
                       ATTN_SMEM);

  // splits + rope tables
  split3_kernel<<<dim3(NEL / 1024, 1, 3), 256>>>(q, k, v, qh, ql, kh, kl, vh,
                                                 vl);
  split4_kernel<<<dim3(WEL / 1024, 1, 4), 256>>>(
      wq, wk, wv, wo, wqh, wql, wkh, wkl, wvh, wvl, woh, wol);
  rope_table_kernel<<<(SS * DK) / 256, 256>>>(ct, st);

  // fused q/k/v projections (+rope on q/k), bf16 plane outputs
  gemm_qkv<<<dim3(8, 32, 3), 256, GEMM_SMEM>>>(
      qh, ql, kh, kl, vh, vl, wqh, wql, wkh, wkl, wvh, wvl, oqh, oql, okh, okl,
      xh, xl, ct, st);

  // attention
  attn_mma<<<dim3(BB * HH, SS / 64), 128, ATTN_SMEM>>>(oqh, oql, okh, okl, xh,
                                                       xl, yh, yl);

  // output projection
  gemm_out<<<dim3(8, 32), 256, GEMM_SMEM>>>(yh, yl, woh, wol, out);
}

// round 11
// speedup vs baseline: 2.6007x; 1.0671x over previous
#include <cuda_runtime.h>
#include <cuda_bf16.h>
#include <math.h>

// Problem constants
#define BB 2
#define SS 2048
#define DD 1024
#define HH 16
#define DK 64
#define NROWS (BB * SS)   // 4096
#define NEL (NROWS * DD)  // 4M
#define WEL (DD * DD)     // 1M

// ---------------------------------------------------------------------------
// Scratch (device globals -- no allocation allowed)
// ---------------------------------------------------------------------------
// input planes
__device__ __nv_bfloat16 g_qh[NEL], g_ql[NEL];
__device__ __nv_bfloat16 g_kh[NEL], g_kl[NEL];
__device__ __nv_bfloat16 g_vh[NEL], g_vl[NEL];
// projection outputs (rope'd q/k, projected v)
__device__ __nv_bfloat16 g_oqh[NEL], g_oql[NEL];
__device__ __nv_bfloat16 g_okh[NEL], g_okl[NEL];
__device__ __nv_bfloat16 g_xh[NEL], g_xl[NEL];
// attention output planes
__device__ __nv_bfloat16 g_yh[NEL], g_yl[NEL];
// weight planes
__device__ __nv_bfloat16 g_wqh[WEL], g_wql[WEL];
__device__ __nv_bfloat16 g_wkh[WEL], g_wkl[WEL];
__device__ __nv_bfloat16 g_wvh[WEL], g_wvl[WEL];
__device__ __nv_bfloat16 g_woh[WEL], g_wol[WEL];
// rope tables [SS][DK]
__device__ float g_ct[SS * DK];
__device__ float g_st[SS * DK];

// ---------------------------------------------------------------------------
// Primitives
// ---------------------------------------------------------------------------
#define LDSM4(R, addr)                                                   \
  asm volatile(                                                          \
      "ldmatrix.sync.aligned.m8n8.x4.shared.b16 {%0,%1,%2,%3},[%4];"     \
      : "=r"((R)[0]), "=r"((R)[1]), "=r"((R)[2]), "=r"((R)[3])           \
      : "r"(addr))

#define LDSM4T(R, addr)                                                  \
  asm volatile(                                                          \
      "ldmatrix.sync.aligned.m8n8.x4.trans.shared.b16 {%0,%1,%2,%3},[%4];" \
      : "=r"((R)[0]), "=r"((R)[1]), "=r"((R)[2]), "=r"((R)[3])           \
      : "r"(addr))

#define MMA16816(C, A, B0, B1)                                           \
  asm volatile(                                                          \
      "mma.sync.aligned.m16n8k16.row.col.f32.bf16.bf16.f32 "             \
      "{%0,%1,%2,%3},{%4,%5,%6,%7},{%8,%9},{%0,%1,%2,%3};"               \
      : "+f"((C)[0]), "+f"((C)[1]), "+f"((C)[2]), "+f"((C)[3])           \
      : "r"((A)[0]), "r"((A)[1]), "r"((A)[2]), "r"((A)[3]), "r"(B0),     \
        "r"(B1))

#define CPA16(dst, src)                                                  \
  asm volatile("cp.async.cg.shared.global [%0], [%1], 16;" ::"r"(dst),   \
               "l"(src))
#define CPA_COMMIT() asm volatile("cp.async.commit_group;" ::)
#define CPA_WAIT(n) asm volatile("cp.async.wait_group %0;" ::"n"(n))

__device__ __forceinline__ unsigned pack_bf16(float a, float b) {
  __nv_bfloat162 t = __halves2bfloat162(__float2bfloat16(a), __float2bfloat16(b));
  return *(unsigned*)&t;
}

// ---------------------------------------------------------------------------
// rope table: ct/st[s][j] = cos/sin(s * 10000^{-(j mod 32)/32}),
// fp32 angle + double range reduction (matches reference numerics).
// ---------------------------------------------------------------------------
__global__ void rope_table_kernel(float* __restrict__ ct,
                                  float* __restrict__ st) {
  int idx = blockIdx.x * blockDim.x + threadIdx.x;  // SS*DK = 131072
  int s = idx >> 6;
  int m = idx & 31;  // j mod 32
  const float L = 0.41524101186091903f;  // log2(10000)/32
  float a = (float)s * exp2f(-(float)m * L);
  const double INV2PI = 0.15915494309189535;
  const double TWOPI = 6.283185307179586;
  double r = (double)a - floor((double)a * INV2PI) * TWOPI;
  ct[idx] = cosf((float)r);
  st[idx] = sinf((float)r);
}

// ---------------------------------------------------------------------------
// batched splits: fp32 -> (hi, lo) bf16 planes. gridDim.z selects tensor.
// ---------------------------------------------------------------------------
__global__ void split3_kernel(const float* __restrict__ x0,
                              const float* __restrict__ x1,
                              const float* __restrict__ x2,
                              __nv_bfloat16* h0, __nv_bfloat16* l0,
                              __nv_bfloat16* h1, __nv_bfloat16* l1,
                              __nv_bfloat16* h2, __nv_bfloat16* l2) {
  const float* x;
  __nv_bfloat16 *hi, *lo;
  if (blockIdx.z == 0) { x = x0; hi = h0; lo = l0; }
  else if (blockIdx.z == 1) { x = x1; hi = h1; lo = l1; }
  else { x = x2; hi = h2; lo = l2; }
  int i = (blockIdx.x * blockDim.x + threadIdx.x) << 2;
  float4 v = *(const float4*)(x + i);
  float f[4] = {v.x, v.y, v.z, v.w};
  __nv_bfloat16 h[4], l[4];
#pragma unroll
  for (int j = 0; j < 4; j++) {
    h[j] = __float2bfloat16(f[j]);
    l[j] = __float2bfloat16(f[j] - __bfloat162float(h[j]));
  }
  *(__nv_bfloat162*)(hi + i) = __halves2bfloat162(h[0], h[1]);
  *(__nv_bfloat162*)(hi + i + 2) = __halves2bfloat162(h[2], h[3]);
  *(__nv_bfloat162*)(lo + i) = __halves2bfloat162(l[0], l[1]);
  *(__nv_bfloat162*)(lo + i + 2) = __halves2bfloat162(l[2], l[3]);
}

__global__ void split4_kernel(const float* __restrict__ x0,
                              const float* __restrict__ x1,
                              const float* __restrict__ x2,
                              const float* __restrict__ x3,
                              __nv_bfloat16* h0, __nv_bfloat16* l0,
                              __nv_bfloat16* h1, __nv_bfloat16* l1,
                              __nv_bfloat16* h2, __nv_bfloat16* l2,
                              __nv_bfloat16* h3, __nv_bfloat16* l3) {
  const float* x;
  __nv_bfloat16 *hi, *lo;
  if (blockIdx.z == 0) { x = x0; hi = h0; lo = l0; }
  else if (blockIdx.z == 1) { x = x1; hi = h1; lo = l1; }
  else if (blockIdx.z == 2) { x = x2; hi = h2; lo = l2; }
  else { x = x3; hi = h3; lo = l3; }
  int i = (blockIdx.x * blockDim.x + threadIdx.x) << 2;
  float4 v = *(const float4*)(x + i);
  float f[4] = {v.x, v.y, v.z, v.w};
  __nv_bfloat16 h[4], l[4];
#pragma unroll
  for (int j = 0; j < 4; j++) {
    h[j] = __float2bfloat16(f[j]);
    l[j] = __float2bfloat16(f[j] - __bfloat162float(h[j]));
  }
  *(__nv_bfloat162*)(hi + i) = __halves2bfloat162(h[0], h[1]);
  *(__nv_bfloat162*)(hi + i + 2) = __halves2bfloat162(h[2], h[3]);
  *(__nv_bfloat162*)(lo + i) = __halves2bfloat162(l[0], l[1]);
  *(__nv_bfloat162*)(lo + i + 2) = __halves2bfloat162(l[2], l[3]);
}

// ---------------------------------------------------------------------------
// GEMM core (cp.async 2-stage, bf16x3). Shared by both GEMM kernels.
// CTA 128x128, K_STEP 32, 8 warps (2m x 4n), warp 64x32.
// ---------------------------------------------------------------------------
#define SA 40
#define PLANE (128 * SA)            // 5120 bf16 per plane
#define BUFE (4 * PLANE)            // AHI, ALO, BHI, BLO
#define GEMM_SMEM (2 * BUFE * 2)    // 81920 bytes

struct GemmCore {
  unsigned sb32;
  const __nv_bfloat16 *xh, *xl, *wh, *wl;
  unsigned sdst;
  int a_r, a_c, b_r, b_c;

  __device__ __forceinline__ void init(const __nv_bfloat16* Xh,
                                       const __nv_bfloat16* Xl,
                                       const __nv_bfloat16* Wh,
                                       const __nv_bfloat16* Wl, int m0, int n0,
                                       unsigned smem_base, int t) {
    sb32 = smem_base;
    const int lane = t & 31;
    const int w = t >> 5;
    const int mw = w & 1;
    const int nw = w >> 1;
    const int grow = t >> 1;
    const int gkh = (t & 1) << 4;
    xh = Xh + (size_t)(m0 + grow) * 1024 + gkh;
    xl = Xl + (size_t)(m0 + grow) * 1024 + gkh;
    wh = Wh + (size_t)(n0 + grow) * 1024 + gkh;
    wl = Wl + (size_t)(n0 + grow) * 1024 + gkh;
    sdst = sb32 + (unsigned)((grow * SA + gkh) << 1);
    a_r = mw * 64 + (lane & 15);
    a_c = (lane & 16) ? 8 : 0;
    b_r = nw * 32 + (lane & 7) + ((lane & 16) ? 8 : 0);
    b_c = (lane & 8) ? 8 : 0;
  }

  __device__ __forceinline__ void issue(int kt, int bufi) {
    const unsigned d = sdst + (unsigned)(bufi * (BUFE * 2));
    const int o_ = kt * 32;
    CPA16(d, xh + o_);
    CPA16(d + 16, xh + o_ + 8);
    CPA16(d + PLANE * 2, xl + o_);
    CPA16(d + PLANE * 2 + 16, xl + o_ + 8);
    CPA16(d + 2 * PLANE * 2, wh + o_);
    CPA16(d + 2 * PLANE * 2 + 16, wh + o_ + 8);
    CPA16(d + 3 * PLANE * 2, wl + o_);
    CPA16(d + 3 * PLANE * 2 + 16, wl + o_ + 8);
    CPA_COMMIT();
  }

  __device__ __forceinline__ void run(float acc[4][4][4]) {
    issue(0, 0);
    CPA_WAIT(0);
    __syncthreads();
    int buf = 0;
    for (int kt = 0; kt < 32; kt++) {
      if (kt < 31) issue(kt + 1, buf ^ 1);
      const unsigned bbase = sb32 + buf * (BUFE * 2);
#pragma unroll
      for (int ks = 0; ks < 2; ks++) {
        const int k0 = ks << 4;
        unsigned ahi[4][4], alo[4][4], bhi[2][4], blo[2][4];
        unsigned aaddr = bbase + (unsigned)((a_r * SA + k0 + a_c) << 1);
#pragma unroll
        for (int mf = 0; mf < 4; mf++) {
          LDSM4(ahi[mf], aaddr + mf * (16 * SA * 2));
          LDSM4(alo[mf], aaddr + mf * (16 * SA * 2) + PLANE * 2);
        }
        unsigned baddr =
            bbase + (unsigned)(((2 * PLANE) + b_r * SA + k0 + b_c) << 1);
#pragma unroll
        for (int nf2 = 0; nf2 < 2; nf2++) {
          LDSM4(bhi[nf2], baddr + nf2 * (16 * SA * 2));
          LDSM4(blo[nf2], baddr + nf2 * (16 * SA * 2) + PLANE * 2);
        }
#pragma unroll
        for (int mf = 0; mf < 4; mf++)
#pragma unroll
          for (int nf = 0; nf < 4; nf++) {
            const int g = nf >> 1, hh = (nf & 1) << 1;
            MMA16816(acc[mf][nf], ahi[mf], bhi[g][hh], bhi[g][hh + 1]);
            MMA16816(acc[mf][nf], ahi[mf], blo[g][hh], blo[g][hh + 1]);
            MMA16816(acc[mf][nf], alo[mf], bhi[g][hh], bhi[g][hh + 1]);
          }
      }
      if (kt < 31) {
        CPA_WAIT(0);
        __syncthreads();
        buf ^= 1;
      }
    }
  }
};

// ---------------------------------------------------------------------------
// Merged q/k/v projection GEMM. grid (8, 32, 3); z: 0=q(rope),1=k(rope),2=v.
// __launch_bounds__(256, 2): cap regs at 128 so 2 CTAs co-reside per SM
// (round-10 ncu showed regs=140 -> 1 CTA/SM -> tensor pipe 42%).
// ---------------------------------------------------------------------------
__global__ __launch_bounds__(256, 2) void gemm_qkv(
    const __nv_bfloat16* __restrict__ Qh, const __nv_bfloat16* __restrict__ Ql,
    const __nv_bfloat16* __restrict__ Kh, const __nv_bfloat16* __restrict__ Kl,
    const __nv_bfloat16* __restrict__ Vh, const __nv_bfloat16* __restrict__ Vl,
    const __nv_bfloat16* __restrict__ Wqh, const __nv_bfloat16* __restrict__ Wql,
    const __nv_bfloat16* __restrict__ Wkh, const __nv_bfloat16* __restrict__ Wkl,
    const __nv_bfloat16* __restrict__ Wvh, const __nv_bfloat16* __restrict__ Wvl,
    __nv_bfloat16* __restrict__ Oqh, __nv_bfloat16* __restrict__ Oql,
    __nv_bfloat16* __restrict__ Okh, __nv_bfloat16* __restrict__ Okl,
    __nv_bfloat16* __restrict__ Ovh, __nv_bfloat16* __restrict__ Ovl,
    const float* __restrict__ CT, const float* __restrict__ ST) {
  extern __shared__ __nv_bfloat16 sb[];
  const int z = blockIdx.z;
  const __nv_bfloat16 *Xh, *Xl, *Wh, *Wl;
  __nv_bfloat16 *Yh, *Yl;
  if (z == 0) { Xh = Qh; Xl = Ql; Wh = Wqh; Wl = Wql; Yh = Oqh; Yl = Oql; }
  else if (z == 1) { Xh = Kh; Xl = Kl; Wh = Wkh; Wl = Wkl; Yh = Okh; Yl = Okl; }
  else { Xh = Vh; Xl = Vl; Wh = Wvh; Wl = Wvl; Yh = Ovh; Yl = Ovl; }

  const int t = threadIdx.x;
  const int lane = t & 31;
  const int w = t >> 5;
  const int m0 = blockIdx.y * 128;
  const int n0 = blockIdx.x * 128;

  GemmCore core;
  core.init(Xh, Xl, Wh, Wl, m0, n0,
            (unsigned)__cvta_generic_to_shared(sb), t);
  float acc[4][4][4] = {};
  core.run(acc);

  const int erow = m0 + (w & 1) * 64 + (lane >> 2);
  const int ecol = n0 + (w >> 1) * 32 + ((lane & 3) << 1);
  const bool dorope = (z < 2);
#pragma unroll
  for (int mf = 0; mf < 4; mf++)
#pragma unroll
    for (int nf = 0; nf < 4; nf++) {
      const int colbase = ecol + nf * 8;
      const int j = colbase & 63;
#pragma unroll
      for (int p = 0; p < 2; p++) {
        const int row = erow + mf * 16 + p * 8;
        float a0 = acc[mf][nf][2 * p], a1 = acc[mf][nf][2 * p + 1];
        if (dorope) {
          const int s = row & (SS - 1);
          float c0 = CT[s * 64 + j], s0v = ST[s * 64 + j];
          float c1 = CT[s * 64 + j + 1], s1v = ST[s * 64 + j + 1];
          float r0 = a0 * c0 - a1 * s0v;
          float r1 = a0 * s1v + a1 * c1;
          a0 = r0;
          a1 = r1;
        }
        __nv_bfloat16 ha = __float2bfloat16(a0), hb = __float2bfloat16(a1);
        size_t addr = (size_t)row * 1024 + colbase;
        *(unsigned*)&Yh[addr] = pack_bf16(a0, a1);
        *(unsigned*)&Yl[addr] = pack_bf16(a0 - __bfloat162float(ha),
                                          a1 - __bfloat162float(hb));
      }
    }
}

// ---------------------------------------------------------------------------
// Final projection GEMM: planes -> fp32 out. Same occupancy fix.
// ---------------------------------------------------------------------------
__global__ __launch_bounds__(256, 2) void gemm_out(
    const __nv_bfloat16* __restrict__ Xh, const __nv_bfloat16* __restrict__ Xl,
    const __nv_bfloat16* __restrict__ Wh, const __nv_bfloat16* __restrict__ Wl,
    float* __restrict__ Y) {
  extern __shared__ __nv_bfloat16 sb[];
  const int t = threadIdx.x;
  const int lane = t & 31;
  const int w = t >> 5;
  const int m0 = blockIdx.y * 128;
  const int n0 = blockIdx.x * 128;

  GemmCore core;
  core.init(Xh, Xl, Wh, Wl, m0, n0,
            (unsigned)__cvta_generic_to_shared(sb), t);
  float acc[4][4][4] = {};
  core.run(acc);

  const int erow = m0 + (w & 1) * 64 + (lane >> 2);
  const int ecol = n0 + (w >> 1) * 32 + ((lane & 3) << 1);
#pragma unroll
  for (int mf = 0; mf < 4; mf++)
#pragma unroll
    for (int nf = 0; nf < 4; nf++) {
      float* yp = Y + (size_t)(erow + mf * 16) * 1024 + ecol + nf * 8;
      float2 lo2 = {acc[mf][nf][0], acc[mf][nf][1]};
      float2 hi2 = {acc[mf][nf][2], acc[mf][nf][3]};
      *(float2*)yp = lo2;
      *(float2*)(yp + 8 * 1024) = hi2;
    }
}

// ---------------------------------------------------------------------------
// MMA flash attention: causal, bf16x3, fp32 softmax/acc, cp.async double
// buffered K/V. CTA = 64 q-rows of one (b,h), 128 threads. Output written
// directly as bf16 hi/lo planes. grid (B*H=32, 32), qt reversed.
// ---------------------------------------------------------------------------
#define AST 72
#define PL2 (64 * AST * 2)          // bytes per plane
#define STAGE_B (4 * PL2)           // bytes per stage (4 planes)
#define ATTN_SMEM (2 * STAGE_B)     // 73728 B

__global__ __launch_bounds__(128, 2) void attn_mma(
    const __nv_bfloat16* __restrict__ Qh, const __nv_bfloat16* __restrict__ Ql,
    const __nv_bfloat16* __restrict__ Kh, const __nv_bfloat16* __restrict__ Kl,
    const __nv_bfloat16* __restrict__ Vh, const __nv_bfloat16* __restrict__ Vl,
    __nv_bfloat16* __restrict__ XoH, __nv_bfloat16* __restrict__ XoL) {
  extern __shared__ __nv_bfloat16 as_[];
  const unsigned s_base = (unsigned)__cvta_generic_to_shared(as_);

  const int t = threadIdx.x;
  const int lane = t & 31;
  const int wi = t >> 5;
  const int b = blockIdx.x >> 4;
  const int h = blockIdx.x & 15;
  const int qt = (int)gridDim.y - 1 - (int)blockIdx.y;
  const size_t base = (size_t)b * SS * DD + h * DK;

  // ---- stage Q tile through buffer-0 planes, pull A-frags to registers ----
  {
    __nv_bfloat16* q0h = as_;
    __nv_bfloat16* q0l = as_ + 64 * AST;
    for (int idx = t; idx < 512; idx += 128) {
      int r = idx >> 3, c = (idx & 7) << 3;
      size_t g = base + (size_t)(qt * 64 + r) * DD + c;
      *(uint4*)&q0h[r * AST + c] = *(const uint4*)&Qh[g];
      *(uint4*)&q0l[r * AST + c] = *(const uint4*)&Ql[g];
    }
  }
  __syncthreads();
  const int a_r = wi * 16 + (lane & 15);
  const int a_c = (lane & 16) ? 8 : 0;
  unsigned qfh[4][4], qfl[4][4];
#pragma unroll
  for (int kc = 0; kc < 4; kc++) {
    unsigned ad = s_base + (unsigned)((a_r * AST + kc * 16 + a_c) << 1);
    LDSM4(qfh[kc], ad);
    LDSM4(qfl[kc], ad + PL2);
  }
  __syncthreads();

  auto issue_tile = [&](int j, int bufi) {
    const unsigned kb = s_base + bufi * STAGE_B;
    for (int idx = t; idx < 512; idx += 128) {
      int r = idx >> 3, c = (idx & 7) << 3;
      size_t g = base + (size_t)(j * 64 + r) * DD + c;
      unsigned off = (unsigned)((r * AST + c) << 1);
      CPA16(kb + off, Kh + g);
      CPA16(kb + PL2 + off, Kl + g);
      CPA16(kb + 2 * PL2 + off, Vh + g);
      CPA16(kb + 3 * PL2 + off, Vl + g);
    }
    CPA_COMMIT();
  };

  const int b_r = (lane & 7) + ((lane & 16) ? 8 : 0);
  const int b_c = (lane & 8) ? 8 : 0;
  const int v_r = lane & 15;
  const int v_c = ((lane >> 4) & 1) << 3;

  float o[8][4] = {};
  float mrow[2] = {-INFINITY, -INFINITY};
  float lrow[2] = {0.f, 0.f};
  const int grow0 = qt * 64 + wi * 16 + (lane >> 2);
  const int gcol0 = (lane & 3) << 1;

  issue_tile(0, 0);
  int buf = 0;
  for (int j = 0; j <= qt; j++) {
    if (j < qt) {
      issue_tile(j + 1, buf ^ 1);
      CPA_WAIT(1);
    } else {
      CPA_WAIT(0);
    }
    __syncthreads();
    const unsigned kb = s_base + buf * STAGE_B;
    const unsigned vb = kb + 2 * PL2;

    // ---- S = Q K^T  (bf16x3) ----
    float sc[8][4] = {};
#pragma unroll
    for (int kc = 0; kc < 4; kc++) {
      unsigned bh[4][4], bl[4][4];
#pragma unroll
      for (int g2 = 0; g2 < 4; g2++) {
        unsigned ad =
            kb + (unsigned)(((g2 * 16 + b_r) * AST + kc * 16 + b_c) << 1);
        LDSM4(bh[g2], ad);
        LDSM4(bl[g2], ad + PL2);
      }
#pragma unroll
      for (int nf = 0; nf < 8; nf++) {
        const int g2 = nf >> 1, hh = (nf & 1) << 1;
        MMA16816(sc[nf], qfh[kc], bh[g2][hh], bh[g2][hh + 1]);
        MMA16816(sc[nf], qfh[kc], bl[g2][hh], bl[g2][hh + 1]);
        MMA16816(sc[nf], qfl[kc], bh[g2][hh], bh[g2][hh + 1]);
      }
    }

    // ---- scale + causal mask ----
    const float SC = 0.125f;  // 1/sqrt(64)
    if (j == qt) {
#pragma unroll
      for (int nf = 0; nf < 8; nf++)
#pragma unroll
        for (int e = 0; e < 4; e++) {
          int col = j * 64 + nf * 8 + gcol0 + (e & 1);
          int row = grow0 + ((e >> 1) << 3);
          sc[nf][e] = (col > row) ? -INFINITY : sc[nf][e] * SC;
        }
    } else {
#pragma unroll
      for (int nf = 0; nf < 8; nf++)
#pragma unroll
        for (int e = 0; e < 4; e++) sc[nf][e] *= SC;
    }

    // ---- online softmax ----
#pragma unroll
    for (int i = 0; i < 2; i++) {
      float tm = -INFINITY;
#pragma unroll
      for (int nf = 0; nf < 8; nf++)
        tm = fmaxf(tm, fmaxf(sc[nf][2 * i], sc[nf][2 * i + 1]));
      tm = fmaxf(tm, __shfl_xor_sync(0xffffffffu, tm, 1));
      tm = fmaxf(tm, __shfl_xor_sync(0xffffffffu, tm, 2));
      float mn = fmaxf(mrow[i], tm);
      float corr = __expf(mrow[i] - mn);
      float ps = 0.f;
#pragma unroll
      for (int nf = 0; nf < 8; nf++) {
        float p0 = __expf(sc[nf][2 * i] - mn);
        float p1 = __expf(sc[nf][2 * i + 1] - mn);
        sc[nf][2 * i] = p0;
        sc[nf][2 * i + 1] = p1;
        ps += p0 + p1;
      }
      ps += __shfl_xor_sync(0xffffffffu, ps, 1);
      ps += __shfl_xor_sync(0xffffffffu, ps, 2);
      lrow[i] = lrow[i] * corr + ps;
      mrow[i] = mn;
#pragma unroll
      for (int nf = 0; nf < 8; nf++) {
        o[nf][2 * i] *= corr;
        o[nf][2 * i + 1] *= corr;
      }
    }

    // ---- O += P V ----
#pragma unroll
    for (int kc = 0; kc < 4; kc++) {
      unsigned pa[4], pl[4];
#pragma unroll
      for (int rr = 0; rr < 2; rr++) {
        float f0 = sc[2 * kc + rr][0], f1 = sc[2 * kc + rr][1];
        float f2 = sc[2 * kc + rr][2], f3 = sc[2 * kc + rr][3];
        __nv_bfloat16 h0 = __float2bfloat16(f0), h1 = __float2bfloat16(f1);
        __nv_bfloat16 h2 = __float2bfloat16(f2), h3 = __float2bfloat16(f3);
        pa[2 * rr] = pack_bf16(f0, f1);
        pa[2 * rr + 1] = pack_bf16(f2, f3);
        pl[2 * rr] = pack_bf16(f0 - __bfloat162float(h0),
                               f1 - __bfloat162float(h1));
        pl[2 * rr + 1] = pack_bf16(f2 - __bfloat162float(h2),
                                   f3 - __bfloat162float(h3));
      }
      unsigned wvh[4][4], wvl[4][4];
#pragma unroll
      for (int g2 = 0; g2 < 4; g2++) {
        unsigned ad =
            vb + (unsigned)(((kc * 16 + v_r) * AST + g2 * 16 + v_c) << 1);
        LDSM4T(wvh[g2], ad);
        LDSM4T(wvl[g2], ad + PL2);
      }
#pragma unroll
      for (int nf = 0; nf < 8; nf++) {
        const int g2 = nf >> 1, hh = (nf & 1) << 1;
        MMA16816(o[nf], pa, wvh[g2][hh], wvh[g2][hh + 1]);
        MMA16816(o[nf], pa, wvl[g2][hh], wvl[g2][hh + 1]);
        MMA16816(o[nf], pl, wvh[g2][hh], wvh[g2][hh + 1]);
      }
    }
    __syncthreads();  // all reads of buf done before next issue overwrites
    buf ^= 1;
  }

  // ---- finalize: write hi/lo planes directly ----
#pragma unroll
  for (int i = 0; i < 2; i++) {
    float inv = 1.f / lrow[i];
    int row = grow0 + i * 8;
#pragma unroll
    for (int nf = 0; nf < 8; nf++) {
      float a = o[nf][2 * i] * inv, b2 = o[nf][2 * i + 1] * inv;
      __nv_bfloat16 ha = __float2bfloat16(a), hb = __float2bfloat16(b2);
      size_t addr = (size_t)(b * SS + row) * DD + h * DK + nf * 8 + gcol0;
      *(unsigned*)&XoH[addr] = pack_bf16(a, b2);
      *(unsigned*)&XoL[addr] =
          pack_bf16(a - __bfloat162float(ha), b2 - __bfloat162float(hb));
    }
  }
}

// ---------------------------------------------------------------------------
// kernel_launch
// Inputs: 0=q, 1=k, 2=v, 3=mask (ignored: tril causal), 4=wq, 5=wk, 6=wv, 7=wo
// ---------------------------------------------------------------------------
extern "C" void kernel_launch(void* const* d_in, const int* in_sizes, int n_in,
                              void* d_out, int out_size) {
  (void)in_sizes; (void)n_in; (void)out_size;
  const float* q = (const float*)d_in[0];
  const float* k = (const float*)d_in[1];
  const float* v = (const float*)d_in[2];
  const float* wq = (const float*)d_in[4];
  const float* wk = (const float*)d_in[5];
  const float* wv = (const float*)d_in[6];
  const float* wo = (const float*)d_in[7];
  float* out = (float*)d_out;

  __nv_bfloat16 *qh, *ql, *kh, *kl, *vh, *vl;
  __nv_bfloat16 *oqh, *oql, *okh, *okl, *xh, *xl, *yh, *yl;
  cudaGetSymbolAddress((void**)&qh, g_qh); cudaGetSymbolAddress((void**)&ql, g_ql);
  cudaGetSymbolAddress((void**)&kh, g_kh); cudaGetSymbolAddress((void**)&kl, g_kl);
  cudaGetSymbolAddress((void**)&vh, g_vh); cudaGetSymbolAddress((void**)&vl, g_vl);
  cudaGetSymbolAddress((void**)&oqh, g_oqh); cudaGetSymbolAddress((void**)&oql, g_oql);
  cudaGetSymbolAddress((void**)&okh, g_okh); cudaGetSymbolAddress((void**)&okl, g_okl);
  cudaGetSymbolAddress((void**)&xh, g_xh); cudaGetSymbolAddress((void**)&xl, g_xl);
  cudaGetSymbolAddress((void**)&yh, g_yh); cudaGetSymbolAddress((void**)&yl, g_yl);
  __nv_bfloat16 *wqh, *wql, *wkh, *wkl, *wvh, *wvl, *woh, *wol;
  cudaGetSymbolAddress((void**)&wqh, g_wqh); cudaGetSymbolAddress((void**)&wql, g_wql);
  cudaGetSymbolAddress((void**)&wkh, g_wkh); cudaGetSymbolAddress((void**)&wkl, g_wkl);
  cudaGetSymbolAddress((void**)&wvh, g_wvh); cudaGetSymbolAddress((void**)&wvl, g_wvl);
  cudaGetSymbolAddress((void**)&woh, g_woh); cudaGetSymbolAddress((void**)&wol, g_wol);
  float *ct, *st;
  cudaGetSymbolAddress((void**)&ct, g_ct);
  cudaGetSymbolAddress((void**)&st, g_st);

  cudaFuncSetAttribute(gemm_qkv, cudaFuncAttributeMaxDynamicSharedMemorySize,
                       GEMM_SMEM);
  cudaFuncSetAttribute(gemm_out, cudaFuncAttributeMaxDynamicSharedMemorySize,
                       GEMM_SMEM);
  cudaFuncSetAttribute(attn_mma, cudaFuncAttributeMaxDynamicSharedMemorySize,
                       ATTN_SMEM);

  // splits + rope tables
  split3_kernel<<<dim3(NEL / 1024, 1, 3), 256>>>(q, k, v, qh, ql, kh, kl, vh,
                                                 vl);
  split4_kernel<<<dim3(WEL / 1024, 1, 4), 256>>>(
      wq, wk, wv, wo, wqh, wql, wkh, wkl, wvh, wvl, woh, wol);
  rope_table_kernel<<<(SS * DK) / 256, 256>>>(ct, st);

  // fused q/k/v projections (+rope on q/k), bf16 plane outputs
  gemm_qkv<<<dim3(8, 32, 3), 256, GEMM_SMEM>>>(
      qh, ql, kh, kl, vh, vl, wqh, wql, wkh, wkl, wvh, wvl, oqh, oql, okh, okl,
      xh, xl, ct, st);

  // attention
  attn_mma<<<dim3(BB * HH, SS / 64), 128, ATTN_SMEM>>>(oqh, oql, okh, okl, xh,
                                                       xl, yh, yl);

  // output projection
  gemm_out<<<dim3(8, 32), 256, GEMM_SMEM>>>(yh, yl, woh, wol, out);
}

// round 14
// speedup vs baseline: 2.6098x; 1.0035x over previous
#include <cuda_runtime.h>
#include <cuda_bf16.h>
#include <math.h>

// Problem constants
#define BB 2
#define SS 2048
#define DD 1024
#define HH 16
#define DK 64
#define NROWS (BB * SS)   // 4096
#define NEL (NROWS * DD)  // 4M
#define WEL (DD * DD)     // 1M

// ---------------------------------------------------------------------------
// Scratch (device globals -- no allocation allowed)
// ---------------------------------------------------------------------------
__device__ __nv_bfloat16 g_qh[NEL], g_ql[NEL];
__device__ __nv_bfloat16 g_kh[NEL], g_kl[NEL];
__device__ __nv_bfloat16 g_vh[NEL], g_vl[NEL];
__device__ __nv_bfloat16 g_oqh[NEL], g_oql[NEL];
__device__ __nv_bfloat16 g_okh[NEL], g_okl[NEL];
__device__ __nv_bfloat16 g_xh[NEL], g_xl[NEL];
__device__ __nv_bfloat16 g_yh[NEL], g_yl[NEL];
__device__ __nv_bfloat16 g_wqh[WEL], g_wql[WEL];
__device__ __nv_bfloat16 g_wkh[WEL], g_wkl[WEL];
__device__ __nv_bfloat16 g_wvh[WEL], g_wvl[WEL];
__device__ __nv_bfloat16 g_woh[WEL], g_wol[WEL];
__device__ float g_ct[SS * DK];
__device__ float g_st[SS * DK];

// ---------------------------------------------------------------------------
// Primitives
// ---------------------------------------------------------------------------
#define LDSM4(R, addr)                                                   \
  asm volatile(                                                          \
      "ldmatrix.sync.aligned.m8n8.x4.shared.b16 {%0,%1,%2,%3},[%4];"     \
      : "=r"((R)[0]), "=r"((R)[1]), "=r"((R)[2]), "=r"((R)[3])           \
      : "r"(addr))

#define LDSM4T(R, addr)                                                  \
  asm volatile(                                                          \
      "ldmatrix.sync.aligned.m8n8.x4.trans.shared.b16 {%0,%1,%2,%3},[%4];" \
      : "=r"((R)[0]), "=r"((R)[1]), "=r"((R)[2]), "=r"((R)[3])           \
      : "r"(addr))

#define MMA16816(C, A, B0, B1)                                           \
  asm volatile(                                                          \
      "mma.sync.aligned.m16n8k16.row.col.f32.bf16.bf16.f32 "             \
      "{%0,%1,%2,%3},{%4,%5,%6,%7},{%8,%9},{%0,%1,%2,%3};"               \
      : "+f"((C)[0]), "+f"((C)[1]), "+f"((C)[2]), "+f"((C)[3])           \
      : "r"((A)[0]), "r"((A)[1]), "r"((A)[2]), "r"((A)[3]), "r"(B0),     \
        "r"(B1))

#define CPA16(dst, src)                                                  \
  asm volatile("cp.async.cg.shared.global [%0], [%1], 16;" ::"r"(dst),   \
               "l"(src))
#define CPA_COMMIT() asm volatile("cp.async.commit_group;" ::)
#define CPA_WAIT(n) asm volatile("cp.async.wait_group %0;" ::"n"(n))

__device__ __forceinline__ unsigned pack_bf16(float a, float b) {
  __nv_bfloat162 t = __halves2bfloat162(__float2bfloat16(a), __float2bfloat16(b));
  return *(unsigned*)&t;
}

// ---------------------------------------------------------------------------
// rope table: ct/st[s][j] = cos/sin(s * 10000^{-(j mod 32)/32})
// ---------------------------------------------------------------------------
__global__ void rope_table_kernel(float* __restrict__ ct,
                                  float* __restrict__ st) {
  int idx = blockIdx.x * blockDim.x + threadIdx.x;  // SS*DK = 131072
  int s = idx >> 6;
  int m = idx & 31;
  const float L = 0.41524101186091903f;  // log2(10000)/32
  float a = (float)s * exp2f(-(float)m * L);
  const double INV2PI = 0.15915494309189535;
  const double TWOPI = 6.283185307179586;
  double r = (double)a - floor((double)a * INV2PI) * TWOPI;
  ct[idx] = cosf((float)r);
  st[idx] = sinf((float)r);
}

// ---------------------------------------------------------------------------
// batched splits: fp32 -> (hi, lo) bf16 planes. gridDim.z selects tensor.
// ---------------------------------------------------------------------------
__global__ void split3_kernel(const float* __restrict__ x0,
                              const float* __restrict__ x1,
                              const float* __restrict__ x2,
                              __nv_bfloat16* h0, __nv_bfloat16* l0,
                              __nv_bfloat16* h1, __nv_bfloat16* l1,
                              __nv_bfloat16* h2, __nv_bfloat16* l2) {
  const float* x;
  __nv_bfloat16 *hi, *lo;
  if (blockIdx.z == 0) { x = x0; hi = h0; lo = l0; }
  else if (blockIdx.z == 1) { x = x1; hi = h1; lo = l1; }
  else { x = x2; hi = h2; lo = l2; }
  int i = (blockIdx.x * blockDim.x + threadIdx.x) << 2;
  float4 v = *(const float4*)(x + i);
  float f[4] = {v.x, v.y, v.z, v.w};
  __nv_bfloat16 h[4], l[4];
#pragma unroll
  for (int j = 0; j < 4; j++) {
    h[j] = __float2bfloat16(f[j]);
    l[j] = __float2bfloat16(f[j] - __bfloat162float(h[j]));
  }
  *(__nv_bfloat162*)(hi + i) = __halves2bfloat162(h[0], h[1]);
  *(__nv_bfloat162*)(hi + i + 2) = __halves2bfloat162(h[2], h[3]);
  *(__nv_bfloat162*)(lo + i) = __halves2bfloat162(l[0], l[1]);
  *(__nv_bfloat162*)(lo + i + 2) = __halves2bfloat162(l[2], l[3]);
}

__global__ void split4_kernel(const float* __restrict__ x0,
                              const float* __restrict__ x1,
                              const float* __restrict__ x2,
                              const float* __restrict__ x3,
                              __nv_bfloat16* h0, __nv_bfloat16* l0,
                              __nv_bfloat16* h1, __nv_bfloat16* l1,
                              __nv_bfloat16* h2, __nv_bfloat16* l2,
                              __nv_bfloat16* h3, __nv_bfloat16* l3) {
  const float* x;
  __nv_bfloat16 *hi, *lo;
  if (blockIdx.z == 0) { x = x0; hi = h0; lo = l0; }
  else if (blockIdx.z == 1) { x = x1; hi = h1; lo = l1; }
  else if (blockIdx.z == 2) { x = x2; hi = h2; lo = l2; }
  else { x = x3; hi = h3; lo = l3; }
  int i = (blockIdx.x * blockDim.x + threadIdx.x) << 2;
  float4 v = *(const float4*)(x + i);
  float f[4] = {v.x, v.y, v.z, v.w};
  __nv_bfloat16 h[4], l[4];
#pragma unroll
  for (int j = 0; j < 4; j++) {
    h[j] = __float2bfloat16(f[j]);
    l[j] = __float2bfloat16(f[j] - __bfloat162float(h[j]));
  }
  *(__nv_bfloat162*)(hi + i) = __halves2bfloat162(h[0], h[1]);
  *(__nv_bfloat162*)(hi + i + 2) = __halves2bfloat162(h[2], h[3]);
  *(__nv_bfloat162*)(lo + i) = __halves2bfloat162(l[0], l[1]);
  *(__nv_bfloat162*)(lo + i + 2) = __halves2bfloat162(l[2], l[3]);
}

// ---------------------------------------------------------------------------
// GEMM core (cp.async 2-stage, bf16x3). CTA 128x128, K_STEP 32,
// 8 warps (2m x 4n), warp 64x32.
// MMA issue order: plane-combo pass OUTERMOST (hh, hl, lh) so consecutive
// asm-volatile HMMAs hit distinct accumulators (no C-operand RAW stalls;
// R11 ncu showed tensor pipe stuck at 47.7% from the dependent triples).
// ---------------------------------------------------------------------------
#define SA 40
#define PLANE (128 * SA)            // 5120 bf16 per plane
#define BUFE (4 * PLANE)            // AHI, ALO, BHI, BLO
#define GEMM_SMEM (2 * BUFE * 2)    // 81920 bytes

struct GemmCore {
  unsigned sb32;
  const __nv_bfloat16 *xh, *xl, *wh, *wl;
  unsigned sdst;
  int a_r, a_c, b_r, b_c;

  __device__ __forceinline__ void init(const __nv_bfloat16* Xh,
                                       const __nv_bfloat16* Xl,
                                       const __nv_bfloat16* Wh,
                                       const __nv_bfloat16* Wl, int m0, int n0,
                                       unsigned smem_base, int t) {
    sb32 = smem_base;
    const int lane = t & 31;
    const int w = t >> 5;
    const int mw = w & 1;
    const int nw = w >> 1;
    const int grow = t >> 1;
    const int gkh = (t & 1) << 4;
    xh = Xh + (size_t)(m0 + grow) * 1024 + gkh;
    xl = Xl + (size_t)(m0 + grow) * 1024 + gkh;
    wh = Wh + (size_t)(n0 + grow) * 1024 + gkh;
    wl = Wl + (size_t)(n0 + grow) * 1024 + gkh;
    sdst = sb32 + (unsigned)((grow * SA + gkh) << 1);
    a_r = mw * 64 + (lane & 15);
    a_c = (lane & 16) ? 8 : 0;
    b_r = nw * 32 + (lane & 7) + ((lane & 16) ? 8 : 0);
    b_c = (lane & 8) ? 8 : 0;
  }

  __device__ __forceinline__ void issue(int kt, int bufi) {
    const unsigned d = sdst + (unsigned)(bufi * (BUFE * 2));
    const int o_ = kt * 32;
    CPA16(d, xh + o_);
    CPA16(d + 16, xh + o_ + 8);
    CPA16(d + PLANE * 2, xl + o_);
    CPA16(d + PLANE * 2 + 16, xl + o_ + 8);
    CPA16(d + 2 * PLANE * 2, wh + o_);
    CPA16(d + 2 * PLANE * 2 + 16, wh + o_ + 8);
    CPA16(d + 3 * PLANE * 2, wl + o_);
    CPA16(d + 3 * PLANE * 2 + 16, wl + o_ + 8);
    CPA_COMMIT();
  }

  __device__ __forceinline__ void run(float acc[4][4][4]) {
    issue(0, 0);
    CPA_WAIT(0);
    __syncthreads();
    int buf = 0;
    for (int kt = 0; kt < 32; kt++) {
      if (kt < 31) issue(kt + 1, buf ^ 1);
      const unsigned bbase = sb32 + buf * (BUFE * 2);
#pragma unroll
      for (int ks = 0; ks < 2; ks++) {
        const int k0 = ks << 4;
        unsigned ahi[4][4], alo[4][4], bhi[2][4], blo[2][4];
        unsigned aaddr = bbase + (unsigned)((a_r * SA + k0 + a_c) << 1);
#pragma unroll
        for (int mf = 0; mf < 4; mf++) {
          LDSM4(ahi[mf], aaddr + mf * (16 * SA * 2));
          LDSM4(alo[mf], aaddr + mf * (16 * SA * 2) + PLANE * 2);
        }
        unsigned baddr =
            bbase + (unsigned)(((2 * PLANE) + b_r * SA + k0 + b_c) << 1);
#pragma unroll
        for (int nf2 = 0; nf2 < 2; nf2++) {
          LDSM4(bhi[nf2], baddr + nf2 * (16 * SA * 2));
          LDSM4(blo[nf2], baddr + nf2 * (16 * SA * 2) + PLANE * 2);
        }
        // 3 passes over 16 independent accumulators
#pragma unroll
        for (int c = 0; c < 3; c++)
#pragma unroll
          for (int mf = 0; mf < 4; mf++)
#pragma unroll
            for (int nf = 0; nf < 4; nf++) {
              const int g = nf >> 1, hh = (nf & 1) << 1;
              if (c == 0)
                MMA16816(acc[mf][nf], ahi[mf], bhi[g][hh], bhi[g][hh + 1]);
              else if (c == 1)
                MMA16816(acc[mf][nf], ahi[mf], blo[g][hh], blo[g][hh + 1]);
              else
                MMA16816(acc[mf][nf], alo[mf], bhi[g][hh], bhi[g][hh + 1]);
            }
      }
      if (kt < 31) {
        CPA_WAIT(0);
        __syncthreads();
        buf ^= 1;
      }
    }
  }
};

// ---------------------------------------------------------------------------
// Merged q/k/v projection GEMM. grid (8, 32, 3); z: 0=q(rope),1=k(rope),2=v.
// __launch_bounds__(256, 2): 2 CTAs/SM (R11 win).
// ---------------------------------------------------------------------------
__global__ __launch_bounds__(256, 2) void gemm_qkv(
    const __nv_bfloat16* __restrict__ Qh, const __nv_bfloat16* __restrict__ Ql,
    const __nv_bfloat16* __restrict__ Kh, const __nv_bfloat16* __restrict__ Kl,
    const __nv_bfloat16* __restrict__ Vh, const __nv_bfloat16* __restrict__ Vl,
    const __nv_bfloat16* __restrict__ Wqh, const __nv_bfloat16* __restrict__ Wql,
    const __nv_bfloat16* __restrict__ Wkh, const __nv_bfloat16* __restrict__ Wkl,
    const __nv_bfloat16* __restrict__ Wvh, const __nv_bfloat16* __restrict__ Wvl,
    __nv_bfloat16* __restrict__ Oqh, __nv_bfloat16* __restrict__ Oql,
    __nv_bfloat16* __restrict__ Okh, __nv_bfloat16* __restrict__ Okl,
    __nv_bfloat16* __restrict__ Ovh, __nv_bfloat16* __restrict__ Ovl,
    const float* __restrict__ CT, const float* __restrict__ ST) {
  extern __shared__ __nv_bfloat16 sb[];
  const int z = blockIdx.z;
  const __nv_bfloat16 *Xh, *Xl, *Wh, *Wl;
  __nv_bfloat16 *Yh, *Yl;
  if (z == 0) { Xh = Qh; Xl = Ql; Wh = Wqh; Wl = Wql; Yh = Oqh; Yl = Oql; }
  else if (z == 1) { Xh = Kh; Xl = Kl; Wh = Wkh; Wl = Wkl; Yh = Okh; Yl = Okl; }
  else { Xh = Vh; Xl = Vl; Wh = Wvh; Wl = Wvl; Yh = Ovh; Yl = Ovl; }

  const int t = threadIdx.x;
  const int lane = t & 31;
  const int w = t >> 5;
  const int m0 = blockIdx.y * 128;
  const int n0 = blockIdx.x * 128;

  GemmCore core;
  core.init(Xh, Xl, Wh, Wl, m0, n0,
            (unsigned)__cvta_generic_to_shared(sb), t);
  float acc[4][4][4] = {};
  core.run(acc);

  const int erow = m0 + (w & 1) * 64 + (lane >> 2);
  const int ecol = n0 + (w >> 1) * 32 + ((lane & 3) << 1);
  const bool dorope = (z < 2);
#pragma unroll
  for (int mf = 0; mf < 4; mf++)
#pragma unroll
    for (int nf = 0; nf < 4; nf++) {
      const int colbase = ecol + nf * 8;
      const int j = colbase & 63;
#pragma unroll
      for (int p = 0; p < 2; p++) {
        const int row = erow + mf * 16 + p * 8;
        float a0 = acc[mf][nf][2 * p], a1 = acc[mf][nf][2 * p + 1];
        if (dorope) {
          const int s = row & (SS - 1);
          float c0 = CT[s * 64 + j], s0v = ST[s * 64 + j];
          float c1 = CT[s * 64 + j + 1], s1v = ST[s * 64 + j + 1];
          float r0 = a0 * c0 - a1 * s0v;
          float r1 = a0 * s1v + a1 * c1;
          a0 = r0;
          a1 = r1;
        }
        __nv_bfloat16 ha = __float2bfloat16(a0), hb = __float2bfloat16(a1);
        size_t addr = (size_t)row * 1024 + colbase;
        *(unsigned*)&Yh[addr] = pack_bf16(a0, a1);
        *(unsigned*)&Yl[addr] = pack_bf16(a0 - __bfloat162float(ha),
                                          a1 - __bfloat162float(hb));
      }
    }
}

// ---------------------------------------------------------------------------
// Final projection GEMM: planes -> fp32 out.
// ---------------------------------------------------------------------------
__global__ __launch_bounds__(256, 2) void gemm_out(
    const __nv_bfloat16* __restrict__ Xh, const __nv_bfloat16* __restrict__ Xl,
    const __nv_bfloat16* __restrict__ Wh, const __nv_bfloat16* __restrict__ Wl,
    float* __restrict__ Y) {
  extern __shared__ __nv_bfloat16 sb[];
  const int t = threadIdx.x;
  const int lane = t & 31;
  const int w = t >> 5;
  const int m0 = blockIdx.y * 128;
  const int n0 = blockIdx.x * 128;

  GemmCore core;
  core.init(Xh, Xl, Wh, Wl, m0, n0,
            (unsigned)__cvta_generic_to_shared(sb), t);
  float acc[4][4][4] = {};
  core.run(acc);

  const int erow = m0 + (w & 1) * 64 + (lane >> 2);
  const int ecol = n0 + (w >> 1) * 32 + ((lane & 3) << 1);
#pragma unroll
  for (int mf = 0; mf < 4; mf++)
#pragma unroll
    for (int nf = 0; nf < 4; nf++) {
      float* yp = Y + (size_t)(erow + mf * 16) * 1024 + ecol + nf * 8;
      float2 lo2 = {acc[mf][nf][0], acc[mf][nf][1]};
      float2 hi2 = {acc[mf][nf][2], acc[mf][nf][3]};
      *(float2*)yp = lo2;
      *(float2*)(yp + 8 * 1024) = hi2;
    }
}

// ---------------------------------------------------------------------------
// MMA flash attention: causal, bf16x3, cp.async double buffered K/V.
// Same MMA-reorder applied (3 passes over 8 independent accumulators).
// ---------------------------------------------------------------------------
#define AST 72
#define PL2 (64 * AST * 2)
#define STAGE_B (4 * PL2)
#define ATTN_SMEM (2 * STAGE_B)  // 73728 B

__global__ __launch_bounds__(128, 2) void attn_mma(
    const __nv_bfloat16* __restrict__ Qh, const __nv_bfloat16* __restrict__ Ql,
    const __nv_bfloat16* __restrict__ Kh, const __nv_bfloat16* __restrict__ Kl,
    const __nv_bfloat16* __restrict__ Vh, const __nv_bfloat16* __restrict__ Vl,
    __nv_bfloat16* __restrict__ XoH, __nv_bfloat16* __restrict__ XoL) {
  extern __shared__ __nv_bfloat16 as_[];
  const unsigned s_base = (unsigned)__cvta_generic_to_shared(as_);

  const int t = threadIdx.x;
  const int lane = t & 31;
  const int wi = t >> 5;
  const int b = blockIdx.x >> 4;
  const int h = blockIdx.x & 15;
  const int qt = (int)gridDim.y - 1 - (int)blockIdx.y;
  const size_t base = (size_t)b * SS * DD + h * DK;

  {
    __nv_bfloat16* q0h = as_;
    __nv_bfloat16* q0l = as_ + 64 * AST;
    for (int idx = t; idx < 512; idx += 128) {
      int r = idx >> 3, c = (idx & 7) << 3;
      size_t g = base + (size_t)(qt * 64 + r) * DD + c;
      *(uint4*)&q0h[r * AST + c] = *(const uint4*)&Qh[g];
      *(uint4*)&q0l[r * AST + c] = *(const uint4*)&Ql[g];
    }
  }
  __syncthreads();
  const int a_r = wi * 16 + (lane & 15);
  const int a_c = (lane & 16) ? 8 : 0;
  unsigned qfh[4][4], qfl[4][4];
#pragma unroll
  for (int kc = 0; kc < 4; kc++) {
    unsigned ad = s_base + (unsigned)((a_r * AST + kc * 16 + a_c) << 1);
    LDSM4(qfh[kc], ad);
    LDSM4(qfl[kc], ad + PL2);
  }
  __syncthreads();

  auto issue_tile = [&](int j, int bufi) {
    const unsigned kb = s_base + bufi * STAGE_B;
    for (int idx = t; idx < 512; idx += 128) {
      int r = idx >> 3, c = (idx & 7) << 3;
      size_t g = base + (size_t)(j * 64 + r) * DD + c;
      unsigned off = (unsigned)((r * AST + c) << 1);
      CPA16(kb + off, Kh + g);
      CPA16(kb + PL2 + off, Kl + g);
      CPA16(kb + 2 * PL2 + off, Vh + g);
      CPA16(kb + 3 * PL2 + off, Vl + g);
    }
    CPA_COMMIT();
  };

  const int b_r = (lane & 7) + ((lane & 16) ? 8 : 0);
  const int b_c = (lane & 8) ? 8 : 0;
  const int v_r = lane & 15;
  const int v_c = ((lane >> 4) & 1) << 3;

  float o[8][4] = {};
  float mrow[2] = {-INFINITY, -INFINITY};
  float lrow[2] = {0.f, 0.f};
  const int grow0 = qt * 64 + wi * 16 + (lane >> 2);
  const int gcol0 = (lane & 3) << 1;

  issue_tile(0, 0);
  int buf = 0;
  for (int j = 0; j <= qt; j++) {
    if (j < qt) {
      issue_tile(j + 1, buf ^ 1);
      CPA_WAIT(1);
    } else {
      CPA_WAIT(0);
    }
    __syncthreads();
    const unsigned kb = s_base + buf * STAGE_B;
    const unsigned vb = kb + 2 * PL2;

    // ---- S = Q K^T  (bf16x3, 3 passes over 8 independent accs per kc) ----
    float sc[8][4] = {};
#pragma unroll
    for (int kc = 0; kc < 4; kc++) {
      unsigned bh[4][4], bl[4][4];
#pragma unroll
      for (int g2 = 0; g2 < 4; g2++) {
        unsigned ad =
            kb + (unsigned)(((g2 * 16 + b_r) * AST + kc * 16 + b_c) << 1);
        LDSM4(bh[g2], ad);
        LDSM4(bl[g2], ad + PL2);
      }
#pragma unroll
      for (int c = 0; c < 3; c++)
#pragma unroll
        for (int nf = 0; nf < 8; nf++) {
          const int g2 = nf >> 1, hh = (nf & 1) << 1;
          if (c == 0)
            MMA16816(sc[nf], qfh[kc], bh[g2][hh], bh[g2][hh + 1]);
          else if (c == 1)
            MMA16816(sc[nf], qfh[kc], bl[g2][hh], bl[g2][hh + 1]);
          else
            MMA16816(sc[nf], qfl[kc], bh[g2][hh], bh[g2][hh + 1]);
        }
    }

    // ---- scale + causal mask ----
    const float SC = 0.125f;  // 1/sqrt(64)
    if (j == qt) {
#pragma unroll
      for (int nf = 0; nf < 8; nf++)
#pragma unroll
        for (int e = 0; e < 4; e++) {
          int col = j * 64 + nf * 8 + gcol0 + (e & 1);
          int row = grow0 + ((e >> 1) << 3);
          sc[nf][e] = (col > row) ? -INFINITY : sc[nf][e] * SC;
        }
    } else {
#pragma unroll
      for (int nf = 0; nf < 8; nf++)
#pragma unroll
        for (int e = 0; e < 4; e++) sc[nf][e] *= SC;
    }

    // ---- online softmax ----
#pragma unroll
    for (int i = 0; i < 2; i++) {
      float tm = -INFINITY;
#pragma unroll
      for (int nf = 0; nf < 8; nf++)
        tm = fmaxf(tm, fmaxf(sc[nf][2 * i], sc[nf][2 * i + 1]));
      tm = fmaxf(tm, __shfl_xor_sync(0xffffffffu, tm, 1));
      tm = fmaxf(tm, __shfl_xor_sync(0xffffffffu, tm, 2));
      float mn = fmaxf(mrow[i], tm);
      float corr = __expf(mrow[i] - mn);
      float ps = 0.f;
#pragma unroll
      for (int nf = 0; nf < 8; nf++) {
        float p0 = __expf(sc[nf][2 * i] - mn);
        float p1 = __expf(sc[nf][2 * i + 1] - mn);
        sc[nf][2 * i] = p0;
        sc[nf][2 * i + 1] = p1;
        ps += p0 + p1;
      }
      ps += __shfl_xor_sync(0xffffffffu, ps, 1);
      ps += __shfl_xor_sync(0xffffffffu, ps, 2);
      lrow[i] = lrow[i] * corr + ps;
      mrow[i] = mn;
#pragma unroll
      for (int nf = 0; nf < 8; nf++) {
        o[nf][2 * i] *= corr;
        o[nf][2 * i + 1] *= corr;
      }
    }

    // ---- O += P V  (3 passes over 8 independent accs per kc) ----
#pragma unroll
    for (int kc = 0; kc < 4; kc++) {
      unsigned pa[4], pl[4];
#pragma unroll
      for (int rr = 0; rr < 2; rr++) {
        float f0 = sc[2 * kc + rr][0], f1 = sc[2 * kc + rr][1];
        float f2 = sc[2 * kc + rr][2], f3 = sc[2 * kc + rr][3];
        __nv_bfloat16 h0 = __float2bfloat16(f0), h1 = __float2bfloat16(f1);
        __nv_bfloat16 h2 = __float2bfloat16(f2), h3 = __float2bfloat16(f3);
        pa[2 * rr] = pack_bf16(f0, f1);
        pa[2 * rr + 1] = pack_bf16(f2, f3);
        pl[2 * rr] = pack_bf16(f0 - __bfloat162float(h0),
                               f1 - __bfloat162float(h1));
        pl[2 * rr + 1] = pack_bf16(f2 - __bfloat162float(h2),
                                   f3 - __bfloat162float(h3));
      }
      unsigned wvh[4][4], wvl[4][4];
#pragma unroll
      for (int g2 = 0; g2 < 4; g2++) {
        unsigned ad =
            vb + (unsigned)(((kc * 16 + v_r) * AST + g2 * 16 + v_c) << 1);
        LDSM4T(wvh[g2], ad);
        LDSM4T(wvl[g2], ad + PL2);
      }
#pragma unroll
      for (int c = 0; c < 3; c++)
#pragma unroll
        for (int nf = 0; nf < 8; nf++) {
          const int g2 = nf >> 1, hh = (nf & 1) << 1;
          if (c == 0)
            MMA16816(o[nf], pa, wvh[g2][hh], wvh[g2][hh + 1]);
          else if (c == 1)
            MMA16816(o[nf], pa, wvl[g2][hh], wvl[g2][hh + 1]);
          else
            MMA16816(o[nf], pl, wvh[g2][hh], wvh[g2][hh + 1]);
        }
    }
    __syncthreads();
    buf ^= 1;
  }

  // ---- finalize: write hi/lo planes directly ----
#pragma unroll
  for (int i = 0; i < 2; i++) {
    float inv = 1.f / lrow[i];
    int row = grow0 + i * 8;
#pragma unroll
    for (int nf = 0; nf < 8; nf++) {
      float a = o[nf][2 * i] * inv, b2 = o[nf][2 * i + 1] * inv;
      __nv_bfloat16 ha = __float2bfloat16(a), hb = __float2bfloat16(b2);
      size_t addr = (size_t)(b * SS + row) * DD + h * DK + nf * 8 + gcol0;
      *(unsigned*)&XoH[addr] = pack_bf16(a, b2);
      *(unsigned*)&XoL[addr] =
          pack_bf16(a - __bfloat162float(ha), b2 - __bfloat162float(hb));
    }
  }
}

// ---------------------------------------------------------------------------
// kernel_launch
// Inputs: 0=q, 1=k, 2=v, 3=mask (ignored: tril causal), 4=wq, 5=wk, 6=wv, 7=wo
// ---------------------------------------------------------------------------
extern "C" void kernel_launch(void* const* d_in, const int* in_sizes, int n_in,
                              void* d_out, int out_size) {
  (void)in_sizes; (void)n_in; (void)out_size;
  const float* q = (const float*)d_in[0];
  const float* k = (const float*)d_in[1];
  const float* v = (const float*)d_in[2];
  const float* wq = (const float*)d_in[4];
  const float* wk = (const float*)d_in[5];
  const float* wv = (const float*)d_in[6];
  const float* wo = (const float*)d_in[7];
  float* out = (float*)d_out;

  __nv_bfloat16 *qh, *ql, *kh, *kl, *vh, *vl;
  __nv_bfloat16 *oqh, *oql, *okh, *okl, *xh, *xl, *yh, *yl;
  cudaGetSymbolAddress((void**)&qh, g_qh); cudaGetSymbolAddress((void**)&ql, g_ql);
  cudaGetSymbolAddress((void**)&kh, g_kh); cudaGetSymbolAddress((void**)&kl, g_kl);
  cudaGetSymbolAddress((void**)&vh, g_vh); cudaGetSymbolAddress((void**)&vl, g_vl);
  cudaGetSymbolAddress((void**)&oqh, g_oqh); cudaGetSymbolAddress((void**)&oql, g_oql);
  cudaGetSymbolAddress((void**)&okh, g_okh); cudaGetSymbolAddress((void**)&okl, g_okl);
  cudaGetSymbolAddress((void**)&xh, g_xh); cudaGetSymbolAddress((void**)&xl, g_xl);
  cudaGetSymbolAddress((void**)&yh, g_yh); cudaGetSymbolAddress((void**)&yl, g_yl);
  __nv_bfloat16 *wqh, *wql, *wkh, *wkl, *wvh, *wvl, *woh, *wol;
  cudaGetSymbolAddress((void**)&wqh, g_wqh); cudaGetSymbolAddress((void**)&wql, g_wql);
  cudaGetSymbolAddress((void**)&wkh, g_wkh); cudaGetSymbolAddress((void**)&wkl, g_wkl);
  cudaGetSymbolAddress((void**)&wvh, g_wvh); cudaGetSymbolAddress((void**)&wvl, g_wvl);
  cudaGetSymbolAddress((void**)&woh, g_woh); cudaGetSymbolAddress((void**)&wol, g_wol);
  float *ct, *st;
  cudaGetSymbolAddress((void**)&ct, g_ct);
  cudaGetSymbolAddress((void**)&st, g_st);

  cudaFuncSetAttribute(gemm_qkv, cudaFuncAttributeMaxDynamicSharedMemorySize,
                       GEMM_SMEM);
  cudaFuncSetAttribute(gemm_out, cudaFuncAttributeMaxDynamicSharedMemorySize,
                       GEMM_SMEM);
  cudaFuncSetAttribute(attn_mma, cudaFuncAttributeMaxDynamicSharedMemorySize,
                       ATTN_SMEM);

  // splits + rope tables
  split3_kernel<<<dim3(NEL / 1024, 1, 3), 256>>>(q, k, v, qh, ql, kh, kl, vh,
                                                 vl);
  split4_kernel<<<dim3(WEL / 1024, 1, 4), 256>>>(
      wq, wk, wv, wo, wqh, wql, wkh, wkl, wvh, wvl, woh, wol);
  rope_table_kernel<<<(SS * DK) / 256, 256>>>(ct, st);

  // fused q/k/v projections (+rope on q/k), bf16 plane outputs
  gemm_qkv<<<dim3(8, 32, 3), 256, GEMM_SMEM>>>(
      qh, ql, kh, kl, vh, vl, wqh, wql, wkh, wkl, wvh, wvl, oqh, oql, okh, okl,
      xh, xl, ct, st);

  // attention
  attn_mma<<<dim3(BB * HH, SS / 64), 128, ATTN_SMEM>>>(oqh, oql, okh, okl, xh,
                                                       xl, yh, yl);

  // output projection
  gemm_out<<<dim3(8, 32), 256, GEMM_SMEM>>>(yh, yl, woh, wol, out);
}